// round 6
// baseline (speedup 1.0000x reference)
#include <cuda_runtime.h>
#include <cstdint>

// Problem dims
#define B_  64
#define T_  1024
#define D_  256
#define H_  512
#define O_  256
#define MROWS (B_ * T_)   // 65536

// ---------------------------------------------------------------------------
// Scratch: two [B,T,H] fp32 buffers (134 MB each) as __device__ globals
// (allocation-free per harness rules).
//  g_xw : layer-0 input projection; overwritten in-place with h0 by scan0,
//         then read as A-operand of the layer-1 input projection.
//  g_x2 : layer-1 input projection; overwritten in-place with h1 by scan1;
//         FC reads g_x2[b][T-1][:].
// ---------------------------------------------------------------------------
__device__ float g_xw[(size_t)B_ * T_ * H_];
__device__ float g_x2[(size_t)B_ * T_ * H_];

// ---------------------------------------------------------------------------
// f32x2 helpers (FFMA2 reaches 128 fp32 MAC/cyc/SM; 3-reg FFMA only 64)
// ---------------------------------------------------------------------------
__device__ __forceinline__ void ffma2(unsigned long long &acc,
                                      unsigned long long a,
                                      unsigned long long b) {
    asm("fma.rn.f32x2 %0, %1, %2, %0;" : "+l"(acc) : "l"(a), "l"(b));
}
__device__ __forceinline__ unsigned long long splat2(float v) {
    unsigned long long r;
    asm("mov.b64 %0, {%1, %1};" : "=l"(r) : "f"(v));
    return r;
}
__device__ __forceinline__ unsigned long long pack2(float lo, float hi) {
    unsigned long long r;
    asm("mov.b64 %0, {%1, %2};" : "=l"(r) : "f"(lo), "f"(hi));
    return r;
}
__device__ __forceinline__ float lo32(unsigned long long u) {
    return __uint_as_float((unsigned)(u & 0xffffffffull));
}
__device__ __forceinline__ float hi32(unsigned long long u) {
    return __uint_as_float((unsigned)(u >> 32));
}

// Accurate tanh that stays accurate even under --use_fast_math
// (fast-math tanhf is only ~2^-11; __expf is ~2 ulp).
__device__ __forceinline__ float tanh_acc(float x) {
    float a = fabsf(x);
    float e = __expf(-2.0f * a);
    float r = (1.0f - e) / (1.0f + e);
    return (x < 0.0f) ? -r : r;
}

__device__ __forceinline__ uint32_t smem_u32(const void* p) {
    uint32_t a;
    asm("{ .reg .u64 t; cvta.to.shared.u64 t, %1; cvt.u32.u64 %0, t; }"
        : "=r"(a) : "l"(p));
    return a;
}

// DSMEM store: write v to the peer CTA (rank) at the same smem offset.
__device__ __forceinline__ void st_cluster_f32(uint32_t addr, int rank, float v) {
    uint32_t rem;
    asm volatile("mapa.shared::cluster.u32 %0, %1, %2;"
                 : "=r"(rem) : "r"(addr), "r"(rank));
    asm volatile("st.shared::cluster.f32 [%0], %1;"
                 :: "r"(rem), "f"(v) : "memory");
}

__device__ __forceinline__ void cluster_barrier() {
    asm volatile("barrier.cluster.arrive.aligned;" ::: "memory");
    asm volatile("barrier.cluster.wait.aligned;"   ::: "memory");
}

// ---------------------------------------------------------------------------
// GEMM: C[M,512] = A[M,K] @ W[512,K]^T + bias1[n] + bias2[n]
// BM=64, BN=64, BK=16, 256 threads, per-thread 4x4 via f32x2 (2 m-pairs x 4 n).
// ---------------------------------------------------------------------------
template <int K>
__global__ __launch_bounds__(256, 2)
void gemm_kernel(const float* __restrict__ A,
                 const float* __restrict__ W,
                 const float* __restrict__ bias1,
                 const float* __restrict__ bias2,
                 float* __restrict__ C)
{
    constexpr int BM = 64, BN = 64, BK = 16, LDSW = 68;  // 68*4B rows, 16B-aligned
    __shared__ float As[BK][LDSW];
    __shared__ float Bs[BK][LDSW];

    const int tid = threadIdx.x;
    const int m0  = blockIdx.x * BM;
    const int n0  = blockIdx.y * BN;
    const int r   = tid >> 2;   // 0..63  (tile row for loading)
    const int c4  = tid & 3;    // 0..3   (float4 column group)
    const int ctm = tid >> 4;   // 0..15  (thread row group)
    const int ctn = tid & 15;   // 0..15  (thread col group)

    unsigned long long acc[2][4];
#pragma unroll
    for (int i = 0; i < 2; i++)
#pragma unroll
        for (int j = 0; j < 4; j++) acc[i][j] = 0ull;

    for (int k0 = 0; k0 < K; k0 += BK) {
        float4 av = *reinterpret_cast<const float4*>(A + (size_t)(m0 + r) * K + k0 + c4 * 4);
        float4 bv = *reinterpret_cast<const float4*>(W + (size_t)(n0 + r) * K + k0 + c4 * 4);
        __syncthreads();   // protect previous iteration's smem reads
        As[c4 * 4 + 0][r] = av.x; As[c4 * 4 + 1][r] = av.y;
        As[c4 * 4 + 2][r] = av.z; As[c4 * 4 + 3][r] = av.w;
        Bs[c4 * 4 + 0][r] = bv.x; Bs[c4 * 4 + 1][r] = bv.y;
        Bs[c4 * 4 + 2][r] = bv.z; Bs[c4 * 4 + 3][r] = bv.w;
        __syncthreads();
#pragma unroll
        for (int k = 0; k < BK; k++) {
            float4 a = *reinterpret_cast<const float4*>(&As[k][ctm * 4]);
            float4 b = *reinterpret_cast<const float4*>(&Bs[k][ctn * 4]);
            unsigned long long ap0 = pack2(a.x, a.y);
            unsigned long long ap1 = pack2(a.z, a.w);
            unsigned long long b0 = splat2(b.x), b1 = splat2(b.y);
            unsigned long long b2 = splat2(b.z), b3 = splat2(b.w);
            ffma2(acc[0][0], ap0, b0); ffma2(acc[0][1], ap0, b1);
            ffma2(acc[0][2], ap0, b2); ffma2(acc[0][3], ap0, b3);
            ffma2(acc[1][0], ap1, b0); ffma2(acc[1][1], ap1, b1);
            ffma2(acc[1][2], ap1, b2); ffma2(acc[1][3], ap1, b3);
        }
    }

    float bia[4];
#pragma unroll
    for (int j = 0; j < 4; j++) {
        int n = n0 + ctn * 4 + j;
        bia[j] = bias1[n] + bias2[n];
    }
#pragma unroll
    for (int mp = 0; mp < 2; mp++) {
        float4 v0, v1;
        v0.x = lo32(acc[mp][0]) + bia[0]; v0.y = lo32(acc[mp][1]) + bia[1];
        v0.z = lo32(acc[mp][2]) + bia[2]; v0.w = lo32(acc[mp][3]) + bia[3];
        v1.x = hi32(acc[mp][0]) + bia[0]; v1.y = hi32(acc[mp][1]) + bia[1];
        v1.z = hi32(acc[mp][2]) + bia[2]; v1.w = hi32(acc[mp][3]) + bia[3];
        int m = m0 + ctm * 4 + mp * 2;
        *reinterpret_cast<float4*>(C + (size_t)m       * H_ + n0 + ctn * 4) = v0;
        *reinterpret_cast<float4*>(C + (size_t)(m + 1) * H_ + n0 + ctn * 4) = v1;
    }
}

// ---------------------------------------------------------------------------
// Recurrent scan. One 8-CTA cluster owns 4 batch chains for all 1024 steps.
// CTA rank r owns hidden slice j in [r*64, r*64+64); its W_hh slice
// (64 rows x 512) lives in REGISTERS (128 regs/thread, persistent).
// Thread (jl = tid&63, kc = tid>>6) computes h for (chain kc, j = rank*64+jl)
// each step, covering k in [kc*128, kc*128+128) of every CTA row and reducing
// 4-way through smem.
//
// h(t) is exchanged between CTAs via DSMEM: each thread stores its produced
// value into the double-buffered hs[] of ALL 8 cluster CTAs with
// mapa + st.shared::cluster, then one cluster barrier per step orders the
// remote stores (PTX-defined release/acquire for shared::cluster). The
// recurrence therefore never reads h from global memory; globals only carry
// the xW stream in and the h stream out (needed by the next layer's GEMM).
// ---------------------------------------------------------------------------
__global__ __launch_bounds__(256, 1) __cluster_dims__(8, 1, 1)
void scan_kernel(float* __restrict__ xw, const float* __restrict__ Whh)
{
    __shared__ float hs[2][4 * H_];     // 16 KB: double-buffered h for 4 chains
    __shared__ float red[4 * 64 * 5];   //  5 KB: [b][jl][kc] partials (pad 5)

    const int tid  = threadIdx.x;
    const int rank = blockIdx.x & 7;
    const int cb   = (blockIdx.x >> 3) * 4;   // first chain of this cluster
    const int jl   = tid & 63;
    const int kc   = tid >> 6;                // 0..3
    const int jg   = rank * 64 + jl;          // global hidden index (owned j)
    const int k0   = kc * 128;

    // W_hh slice -> registers (persistent across all timesteps)
    ulonglong2 Wp[32];
    {
        const ulonglong2* ws =
            reinterpret_cast<const ulonglong2*>(Whh + (size_t)jg * H_ + k0);
#pragma unroll
        for (int i = 0; i < 32; i++) Wp[i] = ws[i];
    }

    // Element this thread owns: (b = cb+kc, j = jg)
    float* own = xw + (size_t)(cb + kc) * T_ * H_ + jg;

    // DSMEM target addresses (this thread's slot in hs[0] / hs[1])
    const uint32_t haddr0 = smem_u32(&hs[0][kc * H_ + jg]);
    const uint32_t haddr1 = haddr0 + 4u * 4 * H_;   // + sizeof(hs[0])

    // ---- t = 0: h0 = tanh(xw), broadcast into buffer 0 ----
    {
        float v = tanh_acc(own[0]);
        own[0] = v;
#pragma unroll
        for (int rr = 0; rr < 8; rr++) st_cluster_f32(haddr0, rr, v);
        cluster_barrier();
    }

    for (int t = 1; t < T_; t++) {
        // Independent of h: issue the xW load early so compute hides it.
        float xwt = own[(size_t)t * H_];

        const float* hb = hs[(t + 1) & 1];     // buffer holding h(t-1)
        const ulonglong2* h0 = reinterpret_cast<const ulonglong2*>(hb + 0 * H_ + k0);
        const ulonglong2* h1 = reinterpret_cast<const ulonglong2*>(hb + 1 * H_ + k0);
        const ulonglong2* h2 = reinterpret_cast<const ulonglong2*>(hb + 2 * H_ + k0);
        const ulonglong2* h3 = reinterpret_cast<const ulonglong2*>(hb + 3 * H_ + k0);

        unsigned long long a0 = 0ull, a1 = 0ull, a2 = 0ull, a3 = 0ull;
#pragma unroll
        for (int i = 0; i < 32; i++) {
            ulonglong2 w  = Wp[i];
            ulonglong2 v0 = h0[i]; ffma2(a0, v0.x, w.x); ffma2(a0, v0.y, w.y);
            ulonglong2 v1 = h1[i]; ffma2(a1, v1.x, w.x); ffma2(a1, v1.y, w.y);
            ulonglong2 v2 = h2[i]; ffma2(a2, v2.x, w.x); ffma2(a2, v2.y, w.y);
            ulonglong2 v3 = h3[i]; ffma2(a3, v3.x, w.x); ffma2(a3, v3.y, w.y);
        }
        red[(0 * 64 + jl) * 5 + kc] = lo32(a0) + hi32(a0);
        red[(1 * 64 + jl) * 5 + kc] = lo32(a1) + hi32(a1);
        red[(2 * 64 + jl) * 5 + kc] = lo32(a2) + hi32(a2);
        red[(3 * 64 + jl) * 5 + kc] = lo32(a3) + hi32(a3);
        __syncthreads();

        const int ri = (kc * 64 + jl) * 5;     // output (b=kc, j=jg)
        float s = red[ri + 0] + red[ri + 1] + red[ri + 2] + red[ri + 3];
        float v = tanh_acc(s + xwt);

        own[(size_t)t * H_] = v;               // in-place: xw slot becomes h

        // Publish h(t) to every CTA's hs[t&1] via DSMEM.
        const uint32_t dst = (t & 1) ? haddr1 : haddr0;
#pragma unroll
        for (int rr = 0; rr < 8; rr++) st_cluster_f32(dst, rr, v);

        // One barrier per step: drains remote stores (release/acquire at
        // cluster scope) and doubles as the CTA-internal phase separator
        // (red[] reads above complete before any thread re-enters).
        cluster_barrier();
    }
}

// ---------------------------------------------------------------------------
// FC: out[b][o] = h1_final[b] . W_fc[o] + b_fc[o]
// ---------------------------------------------------------------------------
__global__ __launch_bounds__(256)
void fc_kernel(const float* __restrict__ hsrc,
               const float* __restrict__ Wfc,
               const float* __restrict__ bfc,
               float* __restrict__ out)
{
    __shared__ float hb[H_];
    const int b = blockIdx.x;
    const int o = threadIdx.x;
    for (int i = o; i < H_; i += 256)
        hb[i] = hsrc[((size_t)b * T_ + (T_ - 1)) * H_ + i];
    __syncthreads();

    const float4* w = reinterpret_cast<const float4*>(Wfc + (size_t)o * H_);
    float acc = 0.0f;
#pragma unroll 8
    for (int i = 0; i < H_ / 4; i++) {
        float4 wv = w[i];
        acc += hb[4 * i + 0] * wv.x + hb[4 * i + 1] * wv.y
             + hb[4 * i + 2] * wv.z + hb[4 * i + 3] * wv.w;
    }
    out[(size_t)b * O_ + o] = acc + bfc[o];
}

// ---------------------------------------------------------------------------
// kernel_launch: 5 graph-capturable kernel launches, stream-ordered.
// ---------------------------------------------------------------------------
extern "C" void kernel_launch(void* const* d_in, const int* in_sizes, int n_in,
                              void* d_out, int out_size)
{
    (void)in_sizes; (void)n_in; (void)out_size;
    const float* x    = (const float*)d_in[0];
    const float* Wih0 = (const float*)d_in[1];
    const float* Whh0 = (const float*)d_in[2];
    const float* bih0 = (const float*)d_in[3];
    const float* bhh0 = (const float*)d_in[4];
    const float* Wih1 = (const float*)d_in[5];
    const float* Whh1 = (const float*)d_in[6];
    const float* bih1 = (const float*)d_in[7];
    const float* bhh1 = (const float*)d_in[8];
    const float* Wfc  = (const float*)d_in[9];
    const float* bfc  = (const float*)d_in[10];

    float *xw = nullptr, *x2 = nullptr;
    cudaGetSymbolAddress((void**)&xw, g_xw);
    cudaGetSymbolAddress((void**)&x2, g_x2);

    dim3 ggrid(MROWS / 64, H_ / 64);   // (1024, 8)

    // Layer 0: input projection (+ both biases), then in-place recurrent scan.
    gemm_kernel<D_><<<ggrid, 256>>>(x, Wih0, bih0, bhh0, xw);
    scan_kernel<<<128, 256>>>(xw, Whh0);

    // Layer 1: input projection reads h0 (now stored in g_xw), then scan.
    gemm_kernel<H_><<<ggrid, 256>>>(xw, Wih1, bih1, bhh1, x2);
    scan_kernel<<<128, 256>>>(x2, Whh1);

    // FC on final hidden state of layer 1.
    fc_kernel<<<B_, 256>>>(x2, Wfc, bfc, (float*)d_out);
}

// round 7
// speedup vs baseline: 1.1579x; 1.1579x over previous
#include <cuda_runtime.h>
#include <cstdint>

// Problem dims
#define B_  64
#define T_  1024
#define D_  256
#define H_  512
#define O_  256
#define MROWS (B_ * T_)   // 65536

// ---------------------------------------------------------------------------
// Scratch (allocation-free per harness rules):
//  g_xw : layer-0 input projection; overwritten in-place with h0 by scan0,
//         then read as A-operand of the layer-1 input projection.
//  g_x2 : layer-1 input projection; scan1 reads it and writes ONLY the final
//         hidden state back (t = T-1); FC reads g_x2[b][T-1][:].
// ---------------------------------------------------------------------------
__device__ float g_xw[(size_t)B_ * T_ * H_];
__device__ float g_x2[(size_t)B_ * T_ * H_];

// ---------------------------------------------------------------------------
// f32x2 helpers (FFMA2 reaches 128 fp32 MAC/cyc/SM; 3-reg FFMA only 64)
// ---------------------------------------------------------------------------
__device__ __forceinline__ void ffma2(unsigned long long &acc,
                                      unsigned long long a,
                                      unsigned long long b) {
    asm("fma.rn.f32x2 %0, %1, %2, %0;" : "+l"(acc) : "l"(a), "l"(b));
}
__device__ __forceinline__ unsigned long long splat2(float v) {
    unsigned long long r;
    asm("mov.b64 %0, {%1, %1};" : "=l"(r) : "f"(v));
    return r;
}
__device__ __forceinline__ unsigned long long pack2(float lo, float hi) {
    unsigned long long r;
    asm("mov.b64 %0, {%1, %2};" : "=l"(r) : "f"(lo), "f"(hi));
    return r;
}
__device__ __forceinline__ float lo32(unsigned long long u) {
    return __uint_as_float((unsigned)(u & 0xffffffffull));
}
__device__ __forceinline__ float hi32(unsigned long long u) {
    return __uint_as_float((unsigned)(u >> 32));
}

// Accurate tanh that stays accurate even under --use_fast_math
__device__ __forceinline__ float tanh_acc(float x) {
    float a = fabsf(x);
    float e = __expf(-2.0f * a);
    float r = (1.0f - e) / (1.0f + e);
    return (x < 0.0f) ? -r : r;
}

__device__ __forceinline__ uint32_t smem_u32(const void* p) {
    uint32_t a;
    asm("{ .reg .u64 t; cvta.to.shared.u64 t, %1; cvt.u32.u64 %0, t; }"
        : "=r"(a) : "l"(p));
    return a;
}

// Vectorized DSMEM store: 16B to peer CTA (rank) at the same smem offset.
__device__ __forceinline__ void st_cluster_v4(uint32_t addr, int rank, float4 v) {
    uint32_t rem;
    asm volatile("mapa.shared::cluster.u32 %0, %1, %2;"
                 : "=r"(rem) : "r"(addr), "r"(rank));
    asm volatile("st.shared::cluster.v4.f32 [%0], {%1, %2, %3, %4};"
                 :: "r"(rem), "f"(v.x), "f"(v.y), "f"(v.z), "f"(v.w)
                 : "memory");
}

__device__ __forceinline__ void cluster_arrive() {
    asm volatile("barrier.cluster.arrive.aligned;" ::: "memory");
}
__device__ __forceinline__ void cluster_wait() {
    asm volatile("barrier.cluster.wait.aligned;" ::: "memory");
}

// ---------------------------------------------------------------------------
// GEMM: C[M,512] = A[M,K] @ W[512,K]^T + bias1[n] + bias2[n]
// BM=64, BN=64, BK=16, 256 threads, per-thread 4x4 via f32x2.
// ---------------------------------------------------------------------------
template <int K>
__global__ __launch_bounds__(256, 2)
void gemm_kernel(const float* __restrict__ A,
                 const float* __restrict__ W,
                 const float* __restrict__ bias1,
                 const float* __restrict__ bias2,
                 float* __restrict__ C)
{
    constexpr int BM = 64, BN = 64, BK = 16, LDSW = 68;
    __shared__ float As[BK][LDSW];
    __shared__ float Bs[BK][LDSW];

    const int tid = threadIdx.x;
    const int m0  = blockIdx.x * BM;
    const int n0  = blockIdx.y * BN;
    const int r   = tid >> 2;
    const int c4  = tid & 3;
    const int ctm = tid >> 4;
    const int ctn = tid & 15;

    unsigned long long acc[2][4];
#pragma unroll
    for (int i = 0; i < 2; i++)
#pragma unroll
        for (int j = 0; j < 4; j++) acc[i][j] = 0ull;

    for (int k0 = 0; k0 < K; k0 += BK) {
        float4 av = *reinterpret_cast<const float4*>(A + (size_t)(m0 + r) * K + k0 + c4 * 4);
        float4 bv = *reinterpret_cast<const float4*>(W + (size_t)(n0 + r) * K + k0 + c4 * 4);
        __syncthreads();
        As[c4 * 4 + 0][r] = av.x; As[c4 * 4 + 1][r] = av.y;
        As[c4 * 4 + 2][r] = av.z; As[c4 * 4 + 3][r] = av.w;
        Bs[c4 * 4 + 0][r] = bv.x; Bs[c4 * 4 + 1][r] = bv.y;
        Bs[c4 * 4 + 2][r] = bv.z; Bs[c4 * 4 + 3][r] = bv.w;
        __syncthreads();
#pragma unroll
        for (int k = 0; k < BK; k++) {
            float4 a = *reinterpret_cast<const float4*>(&As[k][ctm * 4]);
            float4 b = *reinterpret_cast<const float4*>(&Bs[k][ctn * 4]);
            unsigned long long ap0 = pack2(a.x, a.y);
            unsigned long long ap1 = pack2(a.z, a.w);
            unsigned long long b0 = splat2(b.x), b1 = splat2(b.y);
            unsigned long long b2 = splat2(b.z), b3 = splat2(b.w);
            ffma2(acc[0][0], ap0, b0); ffma2(acc[0][1], ap0, b1);
            ffma2(acc[0][2], ap0, b2); ffma2(acc[0][3], ap0, b3);
            ffma2(acc[1][0], ap1, b0); ffma2(acc[1][1], ap1, b1);
            ffma2(acc[1][2], ap1, b2); ffma2(acc[1][3], ap1, b3);
        }
    }

    float bia[4];
#pragma unroll
    for (int j = 0; j < 4; j++) {
        int n = n0 + ctn * 4 + j;
        bia[j] = bias1[n] + bias2[n];
    }
#pragma unroll
    for (int mp = 0; mp < 2; mp++) {
        float4 v0, v1;
        v0.x = lo32(acc[mp][0]) + bia[0]; v0.y = lo32(acc[mp][1]) + bia[1];
        v0.z = lo32(acc[mp][2]) + bia[2]; v0.w = lo32(acc[mp][3]) + bia[3];
        v1.x = hi32(acc[mp][0]) + bia[0]; v1.y = hi32(acc[mp][1]) + bia[1];
        v1.z = hi32(acc[mp][2]) + bia[2]; v1.w = hi32(acc[mp][3]) + bia[3];
        int m = m0 + ctm * 4 + mp * 2;
        *reinterpret_cast<float4*>(C + (size_t)m       * H_ + n0 + ctn * 4) = v0;
        *reinterpret_cast<float4*>(C + (size_t)(m + 1) * H_ + n0 + ctn * 4) = v1;
    }
}

// ---------------------------------------------------------------------------
// Recurrent scan. One 8-CTA cluster owns 4 batch chains for all 1024 steps.
// CTA rank r owns hidden slice j in [r*64, r*64+64); its W_hh slice lives in
// registers (128 regs/thread, persistent). Thread (jl=tid&63, kc=tid>>6)
// computes h for (chain kc, j = rank*64+jl), covering k in [kc*128,+128) and
// reducing 4-way through smem.
//
// h-exchange (the R6 bottleneck, 2048x4B scalar remote stores/CTA/step) is
// now AGGREGATED: produced values go to local hstage[256], then the whole
// 1KB slice is pushed to all 8 CTAs as 512x16B st.shared::cluster.v4 (2 per
// thread). Cluster barrier is split: arrive after the copy, wait at the top
// of the next step after the independent xW LDG.
// ---------------------------------------------------------------------------
template <bool WRITE_ALL>
__global__ __launch_bounds__(256, 1) __cluster_dims__(8, 1, 1)
void scan_kernel(float* __restrict__ xw, const float* __restrict__ Whh)
{
    __shared__ float hs[2][4 * H_];     // 16 KB: double-buffered h, 4 chains
    __shared__ float red[4 * 64 * 5];   //  5 KB: [b][jl][kc] partials (pad 5)
    __shared__ float hstage[256];       //  1 KB: this CTA's produced slice

    const int tid  = threadIdx.x;
    const int rank = blockIdx.x & 7;
    const int cb   = (blockIdx.x >> 3) * 4;   // first chain of this cluster
    const int jl   = tid & 63;
    const int kc   = tid >> 6;                // 0..3
    const int jg   = rank * 64 + jl;          // owned global hidden index
    const int k0   = kc * 128;

    // W_hh slice -> registers (persistent across all timesteps)
    ulonglong2 Wp[32];
    {
        const ulonglong2* ws =
            reinterpret_cast<const ulonglong2*>(Whh + (size_t)jg * H_ + k0);
#pragma unroll
        for (int i = 0; i < 32; i++) Wp[i] = ws[i];
    }

    // Element this thread owns: (b = cb+kc, j = jg)
    float* own = xw + (size_t)(cb + kc) * T_ * H_ + jg;

    // Peer-copy constants: this thread ships float4 #q of the slice to ranks
    // (tid>>6) and (tid>>6)+4. Both jobs share the same chain/offset.
    const int rr0 = tid >> 6;            // 0..3
    const int q   = tid & 63;            // float4 index in 256-float slice
    const int cpc = q >> 4;              // chain 0..3
    const int cpf = q & 15;              // float4 within chain's 64 floats
    const uint32_t hs_base   = smem_u32(&hs[0][0]);
    const uint32_t dst_off   = (uint32_t)(cpc * H_ + rank * 64 + cpf * 4) * 4u;
    const float4*  cp_src    = reinterpret_cast<const float4*>(&hstage[cpc * 64 + cpf * 4]);

    // ---- t = 0: h0 = tanh(xw[0]); publish into buffer 0 ----
    {
        float v = tanh_acc(own[0]);
        if (WRITE_ALL) own[0] = v;
        hstage[tid] = v;                  // hstage[kc*64 + jl] == hstage[tid]
        __syncthreads();
        float4 val = *cp_src;
        uint32_t dst = hs_base + dst_off;            // buffer 0
        st_cluster_v4(dst, rr0,     val);
        st_cluster_v4(dst, rr0 + 4, val);
        cluster_arrive();
    }

    for (int t = 1; t < T_; t++) {
        // Independent of h(t-1): issue before the wait so it overlaps.
        float xwt = own[(size_t)t * H_];

        cluster_wait();                    // h(t-1) fully published

        const float* hb = hs[(t + 1) & 1]; // buffer holding h(t-1)
        const ulonglong2* h0 = reinterpret_cast<const ulonglong2*>(hb + 0 * H_ + k0);
        const ulonglong2* h1 = reinterpret_cast<const ulonglong2*>(hb + 1 * H_ + k0);
        const ulonglong2* h2 = reinterpret_cast<const ulonglong2*>(hb + 2 * H_ + k0);
        const ulonglong2* h3 = reinterpret_cast<const ulonglong2*>(hb + 3 * H_ + k0);

        unsigned long long a0 = 0ull, a1 = 0ull, a2 = 0ull, a3 = 0ull;
#pragma unroll
        for (int i = 0; i < 32; i++) {
            ulonglong2 w  = Wp[i];
            ulonglong2 v0 = h0[i]; ffma2(a0, v0.x, w.x); ffma2(a0, v0.y, w.y);
            ulonglong2 v1 = h1[i]; ffma2(a1, v1.x, w.x); ffma2(a1, v1.y, w.y);
            ulonglong2 v2 = h2[i]; ffma2(a2, v2.x, w.x); ffma2(a2, v2.y, w.y);
            ulonglong2 v3 = h3[i]; ffma2(a3, v3.x, w.x); ffma2(a3, v3.y, w.y);
        }
        red[(0 * 64 + jl) * 5 + kc] = lo32(a0) + hi32(a0);
        red[(1 * 64 + jl) * 5 + kc] = lo32(a1) + hi32(a1);
        red[(2 * 64 + jl) * 5 + kc] = lo32(a2) + hi32(a2);
        red[(3 * 64 + jl) * 5 + kc] = lo32(a3) + hi32(a3);
        __syncthreads();

        const int ri = (kc * 64 + jl) * 5;   // output (b=kc, j=jg)
        float s = red[ri + 0] + red[ri + 1] + red[ri + 2] + red[ri + 3];
        float v = tanh_acc(s + xwt);

        if (WRITE_ALL || t == T_ - 1)
            own[(size_t)t * H_] = v;          // global h (next layer / FC)

        hstage[tid] = v;
        __syncthreads();                      // slice complete

        // Aggregated DSMEM publish: 2 x st.v4 per thread (all 8 ranks).
        float4 val = *cp_src;
        uint32_t dst = hs_base + ((t & 1) ? (uint32_t)(4 * H_) * 4u : 0u) + dst_off;
        st_cluster_v4(dst, rr0,     val);
        st_cluster_v4(dst, rr0 + 4, val);

        cluster_arrive();                     // release: publishes stores
    }
    cluster_wait();                           // pair final arrive before exit
}

// ---------------------------------------------------------------------------
// FC: out[b][o] = h1_final[b] . W_fc[o] + b_fc[o]
// ---------------------------------------------------------------------------
__global__ __launch_bounds__(256)
void fc_kernel(const float* __restrict__ hsrc,
               const float* __restrict__ Wfc,
               const float* __restrict__ bfc,
               float* __restrict__ out)
{
    __shared__ float hb[H_];
    const int b = blockIdx.x;
    const int o = threadIdx.x;
    for (int i = o; i < H_; i += 256)
        hb[i] = hsrc[((size_t)b * T_ + (T_ - 1)) * H_ + i];
    __syncthreads();

    const float4* w = reinterpret_cast<const float4*>(Wfc + (size_t)o * H_);
    float acc = 0.0f;
#pragma unroll 8
    for (int i = 0; i < H_ / 4; i++) {
        float4 wv = w[i];
        acc += hb[4 * i + 0] * wv.x + hb[4 * i + 1] * wv.y
             + hb[4 * i + 2] * wv.z + hb[4 * i + 3] * wv.w;
    }
    out[(size_t)b * O_ + o] = acc + bfc[o];
}

// ---------------------------------------------------------------------------
// kernel_launch: 5 graph-capturable kernel launches, stream-ordered.
// ---------------------------------------------------------------------------
extern "C" void kernel_launch(void* const* d_in, const int* in_sizes, int n_in,
                              void* d_out, int out_size)
{
    (void)in_sizes; (void)n_in; (void)out_size;
    const float* x    = (const float*)d_in[0];
    const float* Wih0 = (const float*)d_in[1];
    const float* Whh0 = (const float*)d_in[2];
    const float* bih0 = (const float*)d_in[3];
    const float* bhh0 = (const float*)d_in[4];
    const float* Wih1 = (const float*)d_in[5];
    const float* Whh1 = (const float*)d_in[6];
    const float* bih1 = (const float*)d_in[7];
    const float* bhh1 = (const float*)d_in[8];
    const float* Wfc  = (const float*)d_in[9];
    const float* bfc  = (const float*)d_in[10];

    float *xw = nullptr, *x2 = nullptr;
    cudaGetSymbolAddress((void**)&xw, g_xw);
    cudaGetSymbolAddress((void**)&x2, g_x2);

    dim3 ggrid(MROWS / 64, H_ / 64);   // (1024, 8)

    // Layer 0: input projection (+ both biases), then in-place recurrent scan.
    gemm_kernel<D_><<<ggrid, 256>>>(x, Wih0, bih0, bhh0, xw);
    scan_kernel<true><<<128, 256>>>(xw, Whh0);

    // Layer 1: input projection reads h0 (stored in g_xw), then scan
    // (writes only the final hidden state).
    gemm_kernel<H_><<<ggrid, 256>>>(xw, Wih1, bih1, bhh1, x2);
    scan_kernel<false><<<128, 256>>>(x2, Whh1);

    // FC on final hidden state of layer 1.
    fc_kernel<<<B_, 256>>>(x2, Wfc, bfc, (float*)d_out);
}

// round 8
// speedup vs baseline: 2.1096x; 1.8219x over previous
#include <cuda_runtime.h>
#include <cstdint>

// Problem dims
#define B_  64
#define T_  1024
#define D_  256
#define H_  512
#define O_  256
#define MROWS (B_ * T_)   // 65536

// ---------------------------------------------------------------------------
// Scratch (allocation-free per harness rules):
//  g_xw : layer-0 input projection; overwritten in-place with h0 by scan0,
//         then read as A-operand of the layer-1 input projection.
//  g_x2 : layer-1 input projection; scan1 writes ONLY the final hidden state
//         back (t = T-1); FC reads g_x2[b][T-1][:].
// ---------------------------------------------------------------------------
__device__ float g_xw[(size_t)B_ * T_ * H_];
__device__ float g_x2[(size_t)B_ * T_ * H_];

// ---------------------------------------------------------------------------
// f32x2 helpers (FFMA2: 2 fp32 MACs per issue)
// ---------------------------------------------------------------------------
__device__ __forceinline__ void ffma2(unsigned long long &acc,
                                      unsigned long long a,
                                      unsigned long long b) {
    asm("fma.rn.f32x2 %0, %1, %2, %0;" : "+l"(acc) : "l"(a), "l"(b));
}
__device__ __forceinline__ unsigned long long splat2(float v) {
    unsigned long long r;
    asm("mov.b64 %0, {%1, %1};" : "=l"(r) : "f"(v));
    return r;
}
__device__ __forceinline__ unsigned long long pack2(float lo, float hi) {
    unsigned long long r;
    asm("mov.b64 %0, {%1, %2};" : "=l"(r) : "f"(lo), "f"(hi));
    return r;
}
__device__ __forceinline__ float lo32(unsigned long long u) {
    return __uint_as_float((unsigned)(u & 0xffffffffull));
}
__device__ __forceinline__ float hi32(unsigned long long u) {
    return __uint_as_float((unsigned)(u >> 32));
}

// Accurate tanh (robust under --use_fast_math)
__device__ __forceinline__ float tanh_acc(float x) {
    float a = fabsf(x);
    float e = __expf(-2.0f * a);
    float r = (1.0f - e) / (1.0f + e);
    return (x < 0.0f) ? -r : r;
}

__device__ __forceinline__ uint32_t smem_u32(const void* p) {
    uint32_t a;
    asm("{ .reg .u64 t; cvta.to.shared.u64 t, %1; cvt.u32.u64 %0, t; }"
        : "=r"(a) : "l"(p));
    return a;
}

// ---- mbarrier / DSMEM bulk primitives ----
__device__ __forceinline__ void mbar_init(uint32_t addr, uint32_t count) {
    asm volatile("mbarrier.init.shared.b64 [%0], %1;" :: "r"(addr), "r"(count) : "memory");
}
__device__ __forceinline__ void mbar_arrive_expect_tx(uint32_t addr, uint32_t bytes) {
    asm volatile("mbarrier.arrive.expect_tx.shared.b64 _, [%0], %1;"
                 :: "r"(addr), "r"(bytes) : "memory");
}
__device__ __forceinline__ void mbar_wait(uint32_t addr, uint32_t parity) {
    asm volatile(
        "{\n\t"
        ".reg .pred P;\n\t"
        "WL_%=:\n\t"
        "mbarrier.try_wait.parity.acquire.cta.shared::cta.b64 P, [%0], %1, 0x989680;\n\t"
        "@!P bra WL_%=;\n\t"
        "}"
        :: "r"(addr), "r"(parity) : "memory");
}
// 1KB smem->peer-smem bulk copy; tx lands on the PEER's mbarrier.
__device__ __forceinline__ void bulk_to_rank(uint32_t dst_local, uint32_t src,
                                             uint32_t mbar_local, int rank) {
    uint32_t dst, rmb;
    asm volatile("mapa.shared::cluster.u32 %0, %1, %2;" : "=r"(dst) : "r"(dst_local), "r"(rank));
    asm volatile("mapa.shared::cluster.u32 %0, %1, %2;" : "=r"(rmb) : "r"(mbar_local), "r"(rank));
    asm volatile(
        "cp.async.bulk.shared::cluster.shared::cta.mbarrier::complete_tx::bytes "
        "[%0], [%1], %2, [%3];"
        :: "r"(dst), "r"(src), "r"(1024), "r"(rmb) : "memory");
}
__device__ __forceinline__ void fence_proxy_async_cta() {
    asm volatile("fence.proxy.async.shared::cta;" ::: "memory");
}
__device__ __forceinline__ void cluster_sync() {
    asm volatile("barrier.cluster.arrive.aligned;" ::: "memory");
    asm volatile("barrier.cluster.wait.aligned;"   ::: "memory");
}

// ---------------------------------------------------------------------------
// GEMM: C[M,512] = A[M,K] @ W[512,K]^T + bias1[n] + bias2[n]   (unchanged)
// ---------------------------------------------------------------------------
template <int K>
__global__ __launch_bounds__(256, 2)
void gemm_kernel(const float* __restrict__ A,
                 const float* __restrict__ W,
                 const float* __restrict__ bias1,
                 const float* __restrict__ bias2,
                 float* __restrict__ C)
{
    constexpr int BM = 64, BN = 64, BK = 16, LDSW = 68;
    __shared__ float As[BK][LDSW];
    __shared__ float Bs[BK][LDSW];

    const int tid = threadIdx.x;
    const int m0  = blockIdx.x * BM;
    const int n0  = blockIdx.y * BN;
    const int r   = tid >> 2;
    const int c4  = tid & 3;
    const int ctm = tid >> 4;
    const int ctn = tid & 15;

    unsigned long long acc[2][4];
#pragma unroll
    for (int i = 0; i < 2; i++)
#pragma unroll
        for (int j = 0; j < 4; j++) acc[i][j] = 0ull;

    for (int k0 = 0; k0 < K; k0 += BK) {
        float4 av = *reinterpret_cast<const float4*>(A + (size_t)(m0 + r) * K + k0 + c4 * 4);
        float4 bv = *reinterpret_cast<const float4*>(W + (size_t)(n0 + r) * K + k0 + c4 * 4);
        __syncthreads();
        As[c4 * 4 + 0][r] = av.x; As[c4 * 4 + 1][r] = av.y;
        As[c4 * 4 + 2][r] = av.z; As[c4 * 4 + 3][r] = av.w;
        Bs[c4 * 4 + 0][r] = bv.x; Bs[c4 * 4 + 1][r] = bv.y;
        Bs[c4 * 4 + 2][r] = bv.z; Bs[c4 * 4 + 3][r] = bv.w;
        __syncthreads();
#pragma unroll
        for (int k = 0; k < BK; k++) {
            float4 a = *reinterpret_cast<const float4*>(&As[k][ctm * 4]);
            float4 b = *reinterpret_cast<const float4*>(&Bs[k][ctn * 4]);
            unsigned long long ap0 = pack2(a.x, a.y);
            unsigned long long ap1 = pack2(a.z, a.w);
            unsigned long long b0 = splat2(b.x), b1 = splat2(b.y);
            unsigned long long b2 = splat2(b.z), b3 = splat2(b.w);
            ffma2(acc[0][0], ap0, b0); ffma2(acc[0][1], ap0, b1);
            ffma2(acc[0][2], ap0, b2); ffma2(acc[0][3], ap0, b3);
            ffma2(acc[1][0], ap1, b0); ffma2(acc[1][1], ap1, b1);
            ffma2(acc[1][2], ap1, b2); ffma2(acc[1][3], ap1, b3);
        }
    }

    float bia[4];
#pragma unroll
    for (int j = 0; j < 4; j++) {
        int n = n0 + ctn * 4 + j;
        bia[j] = bias1[n] + bias2[n];
    }
#pragma unroll
    for (int mp = 0; mp < 2; mp++) {
        float4 v0, v1;
        v0.x = lo32(acc[mp][0]) + bia[0]; v0.y = lo32(acc[mp][1]) + bia[1];
        v0.z = lo32(acc[mp][2]) + bia[2]; v0.w = lo32(acc[mp][3]) + bia[3];
        v1.x = hi32(acc[mp][0]) + bia[0]; v1.y = hi32(acc[mp][1]) + bia[1];
        v1.z = hi32(acc[mp][2]) + bia[2]; v1.w = hi32(acc[mp][3]) + bia[3];
        int m = m0 + ctm * 4 + mp * 2;
        *reinterpret_cast<float4*>(C + (size_t)m       * H_ + n0 + ctn * 4) = v0;
        *reinterpret_cast<float4*>(C + (size_t)(m + 1) * H_ + n0 + ctn * 4) = v1;
    }
}

// ---------------------------------------------------------------------------
// Recurrent scan, barrier-free dataflow version.
//
// One 8-CTA cluster owns 4 batch chains. CTA rank r owns hidden rows
// j in [r*64, r*64+64); W_hh slice register-resident (128 regs/thread).
// h layout in smem is RANK-MAJOR: hs[buf][rank*256 + chain*64 + m] so each
// CTA's produced slice is one contiguous 1KB block.
//
// Per step: the CTA writes its slice to hstage, then ships it to all 8 CTAs
// (incl. self) with 8x cp.async.bulk.shared::cluster (1KB each); every copy
// delivers complete_tx to the DESTINATION CTA's mbarrier. Consumers wait on
// their LOCAL mbarrier for expect_tx = 8KB — no cluster-wide barrier in the
// loop. Two mbarriers + double-buffered hs/hstage give phase separation:
// a CTA cannot publish step t+1 before consuming step t, so phase-(t+2) tx
// can never race phase-t on the same mbarrier, and an in-flight read of
// hstage[b] is always complete before hstage[b] is rewritten (t+2).
// Last step (t = T-1) does not publish, so no tx is in flight at the final
// cluster_sync (which keeps peer smem alive until all copies landed).
// ---------------------------------------------------------------------------
template <bool WRITE_ALL>
__global__ __launch_bounds__(256, 1) __cluster_dims__(8, 1, 1)
void scan_kernel(float* __restrict__ xw, const float* __restrict__ Whh)
{
    __shared__ alignas(16) float hs[2][8 * 256];   // 16 KB, rank-major
    __shared__ alignas(16) float hstage[2][256];   //  2 KB
    __shared__ float red[4 * 64 * 5];              //  5 KB, [b][jl][kc] pad 5
    __shared__ alignas(8) unsigned long long mbar[2];

    const int tid  = threadIdx.x;
    const int rank = blockIdx.x & 7;
    const int cb   = (blockIdx.x >> 3) * 4;   // first chain of this cluster
    const int jl   = tid & 63;
    const int kc   = tid >> 6;                // 0..3
    const int jg   = rank * 64 + jl;          // owned global hidden index
    const int k0   = kc * 128;
    const int r1   = 2 * kc;                  // first rank-block of k-range

    // W_hh slice -> registers. Wp[i] = W[jg][k0+4i .. k0+4i+3].
    ulonglong2 Wp[32];
    {
        const ulonglong2* ws =
            reinterpret_cast<const ulonglong2*>(Whh + (size_t)jg * H_ + k0);
#pragma unroll
        for (int i = 0; i < 32; i++) Wp[i] = ws[i];
    }

    // Element this thread owns: (b = cb+kc, j = jg)
    float* own = xw + (size_t)(cb + kc) * T_ * H_ + jg;

    const uint32_t mb0   = smem_u32(&mbar[0]);
    const uint32_t mb1   = smem_u32(&mbar[1]);
    const uint32_t st0   = smem_u32(&hstage[0][0]);
    const uint32_t hsd0  = smem_u32(&hs[0][rank * 256]);   // my slice in buf0
    constexpr uint32_t HS_BUFB = 8 * 256 * 4;              // bytes per hs buf
    constexpr uint32_t ST_BUFB = 256 * 4;

    if (tid == 0) {
        mbar_init(mb0, 1);
        mbar_init(mb1, 1);
        mbar_arrive_expect_tx(mb0, 8192);   // arm step 0
        mbar_arrive_expect_tx(mb1, 8192);   // arm step 1
    }
    __syncthreads();
    cluster_sync();                          // mbarriers live before any tx

    // ---- t = 0: h0 = tanh(xw[0]); publish into buf 0 ----
    {
        float v = tanh_acc(own[0]);
        if (WRITE_ALL) own[0] = v;
        hstage[0][tid] = v;
        __syncthreads();
        if (tid < 8) {
            fence_proxy_async_cta();
            bulk_to_rank(hsd0, st0, mb0, tid);
        }
    }

    for (int t = 1; t < T_; t++) {
        // Prefetch xW(t) (independent of h(t-1)).
        float xwt = own[(size_t)t * H_];

        const int s   = t - 1;               // step whose data we consume
        const int b   = s & 1;
        const uint32_t mb = b ? mb1 : mb0;
        mbar_wait(mb, (uint32_t)((s >> 1) & 1));
        // Re-arm this mbarrier for step t+1 (its next phase), if published.
        if (tid == 0 && t <= T_ - 3) mbar_arrive_expect_tx(mb, 8192);

        // Compute: h(t-1) lives in hs[b], rank-major.
        const float* hb = hs[b];
        const ulonglong2* pa0 = reinterpret_cast<const ulonglong2*>(hb + r1 * 256 + 0 * 64);
        const ulonglong2* pa1 = reinterpret_cast<const ulonglong2*>(hb + r1 * 256 + 1 * 64);
        const ulonglong2* pa2 = reinterpret_cast<const ulonglong2*>(hb + r1 * 256 + 2 * 64);
        const ulonglong2* pa3 = reinterpret_cast<const ulonglong2*>(hb + r1 * 256 + 3 * 64);
        const ulonglong2* pb0 = pa0 + 64;    // next rank block (+256 floats)
        const ulonglong2* pb1 = pa1 + 64;
        const ulonglong2* pb2 = pa2 + 64;
        const ulonglong2* pb3 = pa3 + 64;

        unsigned long long a0 = 0ull, a1 = 0ull, a2 = 0ull, a3 = 0ull;
#pragma unroll
        for (int i = 0; i < 16; i++) {
            ulonglong2 w = Wp[i];
            ulonglong2 v0 = pa0[i]; ffma2(a0, v0.x, w.x); ffma2(a0, v0.y, w.y);
            ulonglong2 v1 = pa1[i]; ffma2(a1, v1.x, w.x); ffma2(a1, v1.y, w.y);
            ulonglong2 v2 = pa2[i]; ffma2(a2, v2.x, w.x); ffma2(a2, v2.y, w.y);
            ulonglong2 v3 = pa3[i]; ffma2(a3, v3.x, w.x); ffma2(a3, v3.y, w.y);
        }
#pragma unroll
        for (int i = 0; i < 16; i++) {
            ulonglong2 w = Wp[16 + i];
            ulonglong2 v0 = pb0[i]; ffma2(a0, v0.x, w.x); ffma2(a0, v0.y, w.y);
            ulonglong2 v1 = pb1[i]; ffma2(a1, v1.x, w.x); ffma2(a1, v1.y, w.y);
            ulonglong2 v2 = pb2[i]; ffma2(a2, v2.x, w.x); ffma2(a2, v2.y, w.y);
            ulonglong2 v3 = pb3[i]; ffma2(a3, v3.x, w.x); ffma2(a3, v3.y, w.y);
        }
        red[(0 * 64 + jl) * 5 + kc] = lo32(a0) + hi32(a0);
        red[(1 * 64 + jl) * 5 + kc] = lo32(a1) + hi32(a1);
        red[(2 * 64 + jl) * 5 + kc] = lo32(a2) + hi32(a2);
        red[(3 * 64 + jl) * 5 + kc] = lo32(a3) + hi32(a3);
        __syncthreads();

        const int ri = (kc * 64 + jl) * 5;   // output (b = kc, j = jg)
        float sum = red[ri + 0] + red[ri + 1] + red[ri + 2] + red[ri + 3];
        float v = tanh_acc(sum + xwt);

        if (WRITE_ALL || t == T_ - 1)
            own[(size_t)t * H_] = v;          // global h (next layer / FC)

        if (t <= T_ - 2) {
            const int pb = t & 1;
            hstage[pb][tid] = v;
            __syncthreads();                  // slice complete (also fences red)
            if (tid < 8) {
                fence_proxy_async_cta();
                bulk_to_rank(hsd0 + (pb ? HS_BUFB : 0u),
                             st0  + (pb ? ST_BUFB : 0u),
                             pb ? mb1 : mb0, tid);
            }
        } else {
            __syncthreads();                  // protect red[] (loop exit anyway)
        }
    }

    cluster_sync();   // keep smem alive until all inbound copies retired
}

// ---------------------------------------------------------------------------
// FC: out[b][o] = h1_final[b] . W_fc[o] + b_fc[o]
// ---------------------------------------------------------------------------
__global__ __launch_bounds__(256)
void fc_kernel(const float* __restrict__ hsrc,
               const float* __restrict__ Wfc,
               const float* __restrict__ bfc,
               float* __restrict__ out)
{
    __shared__ float hb[H_];
    const int b = blockIdx.x;
    const int o = threadIdx.x;
    for (int i = o; i < H_; i += 256)
        hb[i] = hsrc[((size_t)b * T_ + (T_ - 1)) * H_ + i];
    __syncthreads();

    const float4* w = reinterpret_cast<const float4*>(Wfc + (size_t)o * H_);
    float acc = 0.0f;
#pragma unroll 8
    for (int i = 0; i < H_ / 4; i++) {
        float4 wv = w[i];
        acc += hb[4 * i + 0] * wv.x + hb[4 * i + 1] * wv.y
             + hb[4 * i + 2] * wv.z + hb[4 * i + 3] * wv.w;
    }
    out[(size_t)b * O_ + o] = acc + bfc[o];
}

// ---------------------------------------------------------------------------
// kernel_launch: 5 graph-capturable kernel launches, stream-ordered.
// ---------------------------------------------------------------------------
extern "C" void kernel_launch(void* const* d_in, const int* in_sizes, int n_in,
                              void* d_out, int out_size)
{
    (void)in_sizes; (void)n_in; (void)out_size;
    const float* x    = (const float*)d_in[0];
    const float* Wih0 = (const float*)d_in[1];
    const float* Whh0 = (const float*)d_in[2];
    const float* bih0 = (const float*)d_in[3];
    const float* bhh0 = (const float*)d_in[4];
    const float* Wih1 = (const float*)d_in[5];
    const float* Whh1 = (const float*)d_in[6];
    const float* bih1 = (const float*)d_in[7];
    const float* bhh1 = (const float*)d_in[8];
    const float* Wfc  = (const float*)d_in[9];
    const float* bfc  = (const float*)d_in[10];

    float *xw = nullptr, *x2 = nullptr;
    cudaGetSymbolAddress((void**)&xw, g_xw);
    cudaGetSymbolAddress((void**)&x2, g_x2);

    dim3 ggrid(MROWS / 64, H_ / 64);   // (1024, 8)

    // Layer 0: input projection (+ both biases), then in-place recurrent scan.
    gemm_kernel<D_><<<ggrid, 256>>>(x, Wih0, bih0, bhh0, xw);
    scan_kernel<true><<<128, 256>>>(xw, Whh0);

    // Layer 1: input projection reads h0 (stored in g_xw), then scan
    // (writes only the final hidden state).
    gemm_kernel<H_><<<ggrid, 256>>>(xw, Wih1, bih1, bhh1, x2);
    scan_kernel<false><<<128, 256>>>(x2, Whh1);

    // FC on final hidden state of layer 1.
    fc_kernel<<<B_, 256>>>(x2, Wfc, bfc, (float*)d_out);
}

// round 9
// speedup vs baseline: 2.3399x; 1.1092x over previous
#include <cuda_runtime.h>
#include <cstdint>

// Problem dims
#define B_  64
#define T_  1024
#define D_  256
#define H_  512
#define O_  256
#define MROWS (B_ * T_)   // 65536

// ---------------------------------------------------------------------------
// Scratch (allocation-free per harness rules):
//  g_xw : layer-0 input projection; overwritten in-place with h0 by scan0,
//         then read as A-operand of the layer-1 input projection.
//  g_x2 : layer-1 input projection; scan1 writes ONLY the final hidden state
//         back (t = T-1); FC reads g_x2[b][T-1][:].
// ---------------------------------------------------------------------------
__device__ float g_xw[(size_t)B_ * T_ * H_];
__device__ float g_x2[(size_t)B_ * T_ * H_];

// ---------------------------------------------------------------------------
// f32x2 helpers (FFMA2: 2 fp32 MACs per issue)
// ---------------------------------------------------------------------------
__device__ __forceinline__ void ffma2(unsigned long long &acc,
                                      unsigned long long a,
                                      unsigned long long b) {
    asm("fma.rn.f32x2 %0, %1, %2, %0;" : "+l"(acc) : "l"(a), "l"(b));
}
__device__ __forceinline__ unsigned long long splat2(float v) {
    unsigned long long r;
    asm("mov.b64 %0, {%1, %1};" : "=l"(r) : "f"(v));
    return r;
}
__device__ __forceinline__ unsigned long long pack2(float lo, float hi) {
    unsigned long long r;
    asm("mov.b64 %0, {%1, %2};" : "=l"(r) : "f"(lo), "f"(hi));
    return r;
}
__device__ __forceinline__ float lo32(unsigned long long u) {
    return __uint_as_float((unsigned)(u & 0xffffffffull));
}
__device__ __forceinline__ float hi32(unsigned long long u) {
    return __uint_as_float((unsigned)(u >> 32));
}

// Accurate tanh (robust under --use_fast_math)
__device__ __forceinline__ float tanh_acc(float x) {
    float a = fabsf(x);
    float e = __expf(-2.0f * a);
    float r = (1.0f - e) / (1.0f + e);
    return (x < 0.0f) ? -r : r;
}

__device__ __forceinline__ uint32_t smem_u32(const void* p) {
    uint32_t a;
    asm("{ .reg .u64 t; cvta.to.shared.u64 t, %1; cvt.u32.u64 %0, t; }"
        : "=r"(a) : "l"(p));
    return a;
}

// ---- mbarrier / DSMEM bulk primitives ----
__device__ __forceinline__ void mbar_init(uint32_t addr, uint32_t count) {
    asm volatile("mbarrier.init.shared.b64 [%0], %1;" :: "r"(addr), "r"(count) : "memory");
}
__device__ __forceinline__ void mbar_arrive_expect_tx(uint32_t addr, uint32_t bytes) {
    asm volatile("mbarrier.arrive.expect_tx.shared.b64 _, [%0], %1;"
                 :: "r"(addr), "r"(bytes) : "memory");
}
__device__ __forceinline__ void mbar_wait(uint32_t addr, uint32_t parity) {
    asm volatile(
        "{\n\t"
        ".reg .pred P;\n\t"
        "WL_%=:\n\t"
        "mbarrier.try_wait.parity.acquire.cta.shared::cta.b64 P, [%0], %1, 0x989680;\n\t"
        "@!P bra WL_%=;\n\t"
        "}"
        :: "r"(addr), "r"(parity) : "memory");
}
// 1KB smem->peer-smem bulk copy; tx lands on the PEER's mbarrier.
__device__ __forceinline__ void bulk_to_rank(uint32_t dst_local, uint32_t src,
                                             uint32_t mbar_local, int rank) {
    uint32_t dst, rmb;
    asm volatile("mapa.shared::cluster.u32 %0, %1, %2;" : "=r"(dst) : "r"(dst_local), "r"(rank));
    asm volatile("mapa.shared::cluster.u32 %0, %1, %2;" : "=r"(rmb) : "r"(mbar_local), "r"(rank));
    asm volatile(
        "cp.async.bulk.shared::cluster.shared::cta.mbarrier::complete_tx::bytes "
        "[%0], [%1], %2, [%3];"
        :: "r"(dst), "r"(src), "r"(1024), "r"(rmb) : "memory");
}
__device__ __forceinline__ void fence_proxy_async_cta() {
    asm volatile("fence.proxy.async.shared::cta;" ::: "memory");
}
__device__ __forceinline__ void cluster_sync() {
    asm volatile("barrier.cluster.arrive.aligned;" ::: "memory");
    asm volatile("barrier.cluster.wait.aligned;"   ::: "memory");
}

// ---------------------------------------------------------------------------
// GEMM: C[M,512] = A[M,K] @ W[512,K]^T + bias1[n] + bias2[n]   (unchanged)
// ---------------------------------------------------------------------------
template <int K>
__global__ __launch_bounds__(256, 2)
void gemm_kernel(const float* __restrict__ A,
                 const float* __restrict__ W,
                 const float* __restrict__ bias1,
                 const float* __restrict__ bias2,
                 float* __restrict__ C)
{
    constexpr int BM = 64, BN = 64, BK = 16, LDSW = 68;
    __shared__ float As[BK][LDSW];
    __shared__ float Bs[BK][LDSW];

    const int tid = threadIdx.x;
    const int m0  = blockIdx.x * BM;
    const int n0  = blockIdx.y * BN;
    const int r   = tid >> 2;
    const int c4  = tid & 3;
    const int ctm = tid >> 4;
    const int ctn = tid & 15;

    unsigned long long acc[2][4];
#pragma unroll
    for (int i = 0; i < 2; i++)
#pragma unroll
        for (int j = 0; j < 4; j++) acc[i][j] = 0ull;

    for (int k0 = 0; k0 < K; k0 += BK) {
        float4 av = *reinterpret_cast<const float4*>(A + (size_t)(m0 + r) * K + k0 + c4 * 4);
        float4 bv = *reinterpret_cast<const float4*>(W + (size_t)(n0 + r) * K + k0 + c4 * 4);
        __syncthreads();
        As[c4 * 4 + 0][r] = av.x; As[c4 * 4 + 1][r] = av.y;
        As[c4 * 4 + 2][r] = av.z; As[c4 * 4 + 3][r] = av.w;
        Bs[c4 * 4 + 0][r] = bv.x; Bs[c4 * 4 + 1][r] = bv.y;
        Bs[c4 * 4 + 2][r] = bv.z; Bs[c4 * 4 + 3][r] = bv.w;
        __syncthreads();
#pragma unroll
        for (int k = 0; k < BK; k++) {
            float4 a = *reinterpret_cast<const float4*>(&As[k][ctm * 4]);
            float4 b = *reinterpret_cast<const float4*>(&Bs[k][ctn * 4]);
            unsigned long long ap0 = pack2(a.x, a.y);
            unsigned long long ap1 = pack2(a.z, a.w);
            unsigned long long b0 = splat2(b.x), b1 = splat2(b.y);
            unsigned long long b2 = splat2(b.z), b3 = splat2(b.w);
            ffma2(acc[0][0], ap0, b0); ffma2(acc[0][1], ap0, b1);
            ffma2(acc[0][2], ap0, b2); ffma2(acc[0][3], ap0, b3);
            ffma2(acc[1][0], ap1, b0); ffma2(acc[1][1], ap1, b1);
            ffma2(acc[1][2], ap1, b2); ffma2(acc[1][3], ap1, b3);
        }
    }

    float bia[4];
#pragma unroll
    for (int j = 0; j < 4; j++) {
        int n = n0 + ctn * 4 + j;
        bia[j] = bias1[n] + bias2[n];
    }
#pragma unroll
    for (int mp = 0; mp < 2; mp++) {
        float4 v0, v1;
        v0.x = lo32(acc[mp][0]) + bia[0]; v0.y = lo32(acc[mp][1]) + bia[1];
        v0.z = lo32(acc[mp][2]) + bia[2]; v0.w = lo32(acc[mp][3]) + bia[3];
        v1.x = hi32(acc[mp][0]) + bia[0]; v1.y = hi32(acc[mp][1]) + bia[1];
        v1.z = hi32(acc[mp][2]) + bia[2]; v1.w = hi32(acc[mp][3]) + bia[3];
        int m = m0 + ctm * 4 + mp * 2;
        *reinterpret_cast<float4*>(C + (size_t)m       * H_ + n0 + ctn * 4) = v0;
        *reinterpret_cast<float4*>(C + (size_t)(m + 1) * H_ + n0 + ctn * 4) = v1;
    }
}

// ---------------------------------------------------------------------------
// Recurrent scan, mbarrier dataflow (R8) + latency-hiding compute core (R9).
//
// One 8-CTA cluster owns 4 batch chains. CTA rank r owns hidden rows
// j in [r*64, r*64+64). 512 threads (16 warps): thread (jp = tid&31,
// ks = tid>>5) computes rows j = jp*2, jp*2+1 over k-chunk [ks*32, ks*32+32)
// for all 4 chains. Each h float4 feeds 2 W-rows (LDS:FFMA2 = 1:4);
// W slice register-resident (64 regs/thread).
//
// Reduction: red[16][260] (k-chunk-major): thread writes 8 partials at
// red[ks][out] (2-way conflict max); output thread tid<256 sums
// red[0..16)[tid], applies tanh, writes its h into the local hs slice and
// (when needed) global memory.
//
// h-exchange: producers write the local slice directly in hs (no staging),
// then 7 threads ship the 1KB slice to the 7 PEER CTAs with
// cp.async.bulk.shared::cluster; each copy delivers complete_tx to the
// destination's mbarrier (expect_tx = 7*1024). Consumers wait on their
// LOCAL mbarrier — no cluster-wide barrier in the loop. Two mbarriers +
// double-buffered hs give phase separation (a CTA cannot publish t+1 before
// consuming t, so phase-(t+2) tx can never race phase-t, and hs[b] reads
// for step t-2 always complete before hs[b] is rewritten at step t).
// ---------------------------------------------------------------------------
template <bool WRITE_ALL>
__global__ __launch_bounds__(512, 1) __cluster_dims__(8, 1, 1)
void scan_kernel(float* __restrict__ xw, const float* __restrict__ Whh)
{
    __shared__ alignas(16) float hs[2][8 * 256];   // 16 KB, rank-major h
    __shared__ alignas(16) float red[16][260];     // 16.6 KB partials
    __shared__ alignas(8) unsigned long long mbar[2];

    const int tid  = threadIdx.x;
    const int rank = blockIdx.x & 7;
    const int cb   = (blockIdx.x >> 3) * 4;   // first chain of this cluster
    const int jp   = tid & 31;                // j-pair index (rows 2jp, 2jp+1)
    const int ks   = tid >> 5;                // k-chunk 0..15 (== warp id)
    const int jg0  = rank * 64 + jp * 2;      // first owned W row
    const int k0   = ks * 32;

    // W_hh rows jg0, jg0+1 over k-chunk -> registers (persistent).
    ulonglong2 Wa[8], Wb[8];
    {
        const ulonglong2* w0 =
            reinterpret_cast<const ulonglong2*>(Whh + (size_t)jg0 * H_ + k0);
        const ulonglong2* w1 =
            reinterpret_cast<const ulonglong2*>(Whh + (size_t)(jg0 + 1) * H_ + k0);
#pragma unroll
        for (int i = 0; i < 8; i++) { Wa[i] = w0[i]; Wb[i] = w1[i]; }
    }

    // Output role (tid < 256): chain c = tid>>6, j = tid&63, out index = tid.
    const int oc = (tid >> 6) & 3;
    const int oj = tid & 63;
    float* own = xw + (size_t)(cb + oc) * T_ * H_ + rank * 64 + oj;
    const bool is_prod = (tid < 256);

    const uint32_t mb0  = smem_u32(&mbar[0]);
    const uint32_t mb1  = smem_u32(&mbar[1]);
    const uint32_t hsd0 = smem_u32(&hs[0][rank * 256]);   // my slice, buf0
    constexpr uint32_t HS_BUFB = 8 * 256 * 4;             // bytes per hs buf

    if (tid == 0) {
        mbar_init(mb0, 1);
        mbar_init(mb1, 1);
        mbar_arrive_expect_tx(mb0, 7168);   // arm step 0 (7 peer slices)
        mbar_arrive_expect_tx(mb1, 7168);   // arm step 1
    }
    __syncthreads();
    cluster_sync();                          // mbarriers live before any tx

    // h-chunk base offset inside a buffer for this thread's k-range:
    // global k = ks*32 .. +32 lives in rank-block (ks>>1), chain stride 64.
    const int hoff = (ks >> 1) * 256 + (ks & 1) * 32;

    // ---- t = 0: h0 = tanh(xw[0]); local slice + publish into buf 0 ----
    {
        if (is_prod) {
            float v = tanh_acc(own[0]);
            if (WRITE_ALL) own[0] = v;
            hs[0][rank * 256 + tid] = v;     // slice layout = chain*64 + j
        }
        __syncthreads();
        if (tid < 8 && tid != rank) {
            fence_proxy_async_cta();
            bulk_to_rank(hsd0, hsd0, mb0, tid);
        }
    }

    for (int t = 1; t < T_; t++) {
        // Prefetch xW(t) (independent of h(t-1)).
        float xwt = is_prod ? own[(size_t)t * H_] : 0.0f;

        const int s = t - 1;                 // step whose data we consume
        const int b = s & 1;
        const uint32_t mb = b ? mb1 : mb0;
        mbar_wait(mb, (uint32_t)((s >> 1) & 1));
        // Re-arm this mbarrier for step t+1 (its next phase), if published.
        if (tid == 0 && t <= T_ - 3) mbar_arrive_expect_tx(mb, 7168);

        // Compute: h(t-1) in hs[b]. 4 chains x 2 rows, k-chunk of 32.
        const float* hb = hs[b] + hoff;
        const ulonglong2* p0 = reinterpret_cast<const ulonglong2*>(hb + 0 * 64);
        const ulonglong2* p1 = reinterpret_cast<const ulonglong2*>(hb + 1 * 64);
        const ulonglong2* p2 = reinterpret_cast<const ulonglong2*>(hb + 2 * 64);
        const ulonglong2* p3 = reinterpret_cast<const ulonglong2*>(hb + 3 * 64);

        unsigned long long a00 = 0ull, a01 = 0ull;   // chain 0, rows 0/1
        unsigned long long a10 = 0ull, a11 = 0ull;
        unsigned long long a20 = 0ull, a21 = 0ull;
        unsigned long long a30 = 0ull, a31 = 0ull;
#pragma unroll
        for (int i = 0; i < 8; i++) {
            ulonglong2 w0 = Wa[i], w1 = Wb[i];
            ulonglong2 v0 = p0[i];
            ffma2(a00, v0.x, w0.x); ffma2(a00, v0.y, w0.y);
            ffma2(a01, v0.x, w1.x); ffma2(a01, v0.y, w1.y);
            ulonglong2 v1 = p1[i];
            ffma2(a10, v1.x, w0.x); ffma2(a10, v1.y, w0.y);
            ffma2(a11, v1.x, w1.x); ffma2(a11, v1.y, w1.y);
            ulonglong2 v2 = p2[i];
            ffma2(a20, v2.x, w0.x); ffma2(a20, v2.y, w0.y);
            ffma2(a21, v2.x, w1.x); ffma2(a21, v2.y, w1.y);
            ulonglong2 v3 = p3[i];
            ffma2(a30, v3.x, w0.x); ffma2(a30, v3.y, w0.y);
            ffma2(a31, v3.x, w1.x); ffma2(a31, v3.y, w1.y);
        }
        {
            const int j0 = jp * 2, j1 = jp * 2 + 1;
            red[ks][0 * 64 + j0] = lo32(a00) + hi32(a00);
            red[ks][0 * 64 + j1] = lo32(a01) + hi32(a01);
            red[ks][1 * 64 + j0] = lo32(a10) + hi32(a10);
            red[ks][1 * 64 + j1] = lo32(a11) + hi32(a11);
            red[ks][2 * 64 + j0] = lo32(a20) + hi32(a20);
            red[ks][2 * 64 + j1] = lo32(a21) + hi32(a21);
            red[ks][3 * 64 + j0] = lo32(a30) + hi32(a30);
            red[ks][3 * 64 + j1] = lo32(a31) + hi32(a31);
        }
        __syncthreads();

        if (is_prod) {
            float s0 = red[0][tid]  + red[1][tid]  + red[2][tid]  + red[3][tid];
            float s1 = red[4][tid]  + red[5][tid]  + red[6][tid]  + red[7][tid];
            float s2 = red[8][tid]  + red[9][tid]  + red[10][tid] + red[11][tid];
            float s3 = red[12][tid] + red[13][tid] + red[14][tid] + red[15][tid];
            float v = tanh_acc(((s0 + s1) + (s2 + s3)) + xwt);

            if (WRITE_ALL || t == T_ - 1)
                own[(size_t)t * H_] = v;      // global h (next layer / FC)

            if (t <= T_ - 2)
                hs[t & 1][rank * 256 + tid] = v;
        }
        __syncthreads();                      // slice complete / red[] safe

        if (t <= T_ - 2 && tid < 8 && tid != rank) {
            const uint32_t boff = (t & 1) ? HS_BUFB : 0u;
            fence_proxy_async_cta();
            bulk_to_rank(hsd0 + boff, hsd0 + boff, (t & 1) ? mb1 : mb0, tid);
        }
    }

    cluster_sync();   // keep smem alive until all inbound copies retired
}

// ---------------------------------------------------------------------------
// FC: out[b][o] = h1_final[b] . W_fc[o] + b_fc[o]
// ---------------------------------------------------------------------------
__global__ __launch_bounds__(256)
void fc_kernel(const float* __restrict__ hsrc,
               const float* __restrict__ Wfc,
               const float* __restrict__ bfc,
               float* __restrict__ out)
{
    __shared__ float hb[H_];
    const int b = blockIdx.x;
    const int o = threadIdx.x;
    for (int i = o; i < H_; i += 256)
        hb[i] = hsrc[((size_t)b * T_ + (T_ - 1)) * H_ + i];
    __syncthreads();

    const float4* w = reinterpret_cast<const float4*>(Wfc + (size_t)o * H_);
    float acc = 0.0f;
#pragma unroll 8
    for (int i = 0; i < H_ / 4; i++) {
        float4 wv = w[i];
        acc += hb[4 * i + 0] * wv.x + hb[4 * i + 1] * wv.y
             + hb[4 * i + 2] * wv.z + hb[4 * i + 3] * wv.w;
    }
    out[(size_t)b * O_ + o] = acc + bfc[o];
}

// ---------------------------------------------------------------------------
// kernel_launch: 5 graph-capturable kernel launches, stream-ordered.
// ---------------------------------------------------------------------------
extern "C" void kernel_launch(void* const* d_in, const int* in_sizes, int n_in,
                              void* d_out, int out_size)
{
    (void)in_sizes; (void)n_in; (void)out_size;
    const float* x    = (const float*)d_in[0];
    const float* Wih0 = (const float*)d_in[1];
    const float* Whh0 = (const float*)d_in[2];
    const float* bih0 = (const float*)d_in[3];
    const float* bhh0 = (const float*)d_in[4];
    const float* Wih1 = (const float*)d_in[5];
    const float* Whh1 = (const float*)d_in[6];
    const float* bih1 = (const float*)d_in[7];
    const float* bhh1 = (const float*)d_in[8];
    const float* Wfc  = (const float*)d_in[9];
    const float* bfc  = (const float*)d_in[10];

    float *xw = nullptr, *x2 = nullptr;
    cudaGetSymbolAddress((void**)&xw, g_xw);
    cudaGetSymbolAddress((void**)&x2, g_x2);

    dim3 ggrid(MROWS / 64, H_ / 64);   // (1024, 8)

    // Layer 0: input projection (+ both biases), then in-place recurrent scan.
    gemm_kernel<D_><<<ggrid, 256>>>(x, Wih0, bih0, bhh0, xw);
    scan_kernel<true><<<128, 512>>>(xw, Whh0);

    // Layer 1: input projection reads h0 (stored in g_xw), then scan
    // (writes only the final hidden state).
    gemm_kernel<H_><<<ggrid, 256>>>(xw, Wih1, bih1, bhh1, x2);
    scan_kernel<false><<<128, 512>>>(x2, Whh1);

    // FC on final hidden state of layer 1.
    fc_kernel<<<B_, 256>>>(x2, Wfc, bfc, (float*)d_out);
}

// round 10
// speedup vs baseline: 2.4226x; 1.0353x over previous
#include <cuda_runtime.h>
#include <cstdint>

// Problem dims
#define B_  64
#define T_  1024
#define D_  256
#define H_  512
#define O_  256
#define MROWS (B_ * T_)   // 65536

// ---------------------------------------------------------------------------
// Scratch (allocation-free per harness rules):
//  g_xw : layer-0 input projection; overwritten in-place with h0 by scan0,
//         then read as A-operand of the layer-1 input projection.
//  g_x2 : layer-1 input projection; scan1 writes ONLY the final hidden state
//         back (t = T-1); FC reads g_x2[b][T-1][:].
// ---------------------------------------------------------------------------
__device__ float g_xw[(size_t)B_ * T_ * H_];
__device__ float g_x2[(size_t)B_ * T_ * H_];

// ---------------------------------------------------------------------------
// f32x2 helpers (FFMA2: 2 fp32 MACs per issue)
// ---------------------------------------------------------------------------
__device__ __forceinline__ void ffma2(unsigned long long &acc,
                                      unsigned long long a,
                                      unsigned long long b) {
    asm("fma.rn.f32x2 %0, %1, %2, %0;" : "+l"(acc) : "l"(a), "l"(b));
}
__device__ __forceinline__ unsigned long long splat2(float v) {
    unsigned long long r;
    asm("mov.b64 %0, {%1, %1};" : "=l"(r) : "f"(v));
    return r;
}
__device__ __forceinline__ unsigned long long pack2(float lo, float hi) {
    unsigned long long r;
    asm("mov.b64 %0, {%1, %2};" : "=l"(r) : "f"(lo), "f"(hi));
    return r;
}
__device__ __forceinline__ float lo32(unsigned long long u) {
    return __uint_as_float((unsigned)(u & 0xffffffffull));
}
__device__ __forceinline__ float hi32(unsigned long long u) {
    return __uint_as_float((unsigned)(u >> 32));
}

// Accurate tanh (robust under --use_fast_math)
__device__ __forceinline__ float tanh_acc(float x) {
    float a = fabsf(x);
    float e = __expf(-2.0f * a);
    float r = (1.0f - e) / (1.0f + e);
    return (x < 0.0f) ? -r : r;
}

__device__ __forceinline__ uint32_t smem_u32(const void* p) {
    uint32_t a;
    asm("{ .reg .u64 t; cvta.to.shared.u64 t, %1; cvt.u32.u64 %0, t; }"
        : "=r"(a) : "l"(p));
    return a;
}

// ---- mbarrier / DSMEM primitives ----
__device__ __forceinline__ void mbar_init(uint32_t addr, uint32_t count) {
    asm volatile("mbarrier.init.shared.b64 [%0], %1;" :: "r"(addr), "r"(count) : "memory");
}
__device__ __forceinline__ void mbar_arrive_expect_tx(uint32_t addr, uint32_t bytes) {
    asm volatile("mbarrier.arrive.expect_tx.shared.b64 _, [%0], %1;"
                 :: "r"(addr), "r"(bytes) : "memory");
}
__device__ __forceinline__ void mbar_wait(uint32_t addr, uint32_t parity) {
    asm volatile(
        "{\n\t"
        ".reg .pred P;\n\t"
        "WL_%=:\n\t"
        "mbarrier.try_wait.parity.acquire.cta.shared::cta.b64 P, [%0], %1, 0x989680;\n\t"
        "@!P bra WL_%=;\n\t"
        "}"
        :: "r"(addr), "r"(parity) : "memory");
}
// Direct remote smem store (SM->SM fabric, NOT the TMA/bulk engine):
// 16B to peer CTA `rank` at this smem offset; tx lands on the PEER's mbarrier.
__device__ __forceinline__ void st_async_v4(uint32_t dst_local, uint32_t mbar_local,
                                            int rank, uint4 v) {
    uint32_t dst, rmb;
    asm volatile("mapa.shared::cluster.u32 %0, %1, %2;" : "=r"(dst) : "r"(dst_local), "r"(rank));
    asm volatile("mapa.shared::cluster.u32 %0, %1, %2;" : "=r"(rmb) : "r"(mbar_local), "r"(rank));
    asm volatile(
        "st.async.shared::cluster.mbarrier::complete_tx::bytes.v4.b32 "
        "[%0], {%1, %2, %3, %4}, [%5];"
        :: "r"(dst), "r"(v.x), "r"(v.y), "r"(v.z), "r"(v.w), "r"(rmb) : "memory");
}
__device__ __forceinline__ void cluster_sync() {
    asm volatile("barrier.cluster.arrive.aligned;" ::: "memory");
    asm volatile("barrier.cluster.wait.aligned;"   ::: "memory");
}

// ---------------------------------------------------------------------------
// GEMM: C[M,512] = A[M,K] @ W[512,K]^T + bias1[n] + bias2[n]   (unchanged)
// ---------------------------------------------------------------------------
template <int K>
__global__ __launch_bounds__(256, 2)
void gemm_kernel(const float* __restrict__ A,
                 const float* __restrict__ W,
                 const float* __restrict__ bias1,
                 const float* __restrict__ bias2,
                 float* __restrict__ C)
{
    constexpr int BM = 64, BN = 64, BK = 16, LDSW = 68;
    __shared__ float As[BK][LDSW];
    __shared__ float Bs[BK][LDSW];

    const int tid = threadIdx.x;
    const int m0  = blockIdx.x * BM;
    const int n0  = blockIdx.y * BN;
    const int r   = tid >> 2;
    const int c4  = tid & 3;
    const int ctm = tid >> 4;
    const int ctn = tid & 15;

    unsigned long long acc[2][4];
#pragma unroll
    for (int i = 0; i < 2; i++)
#pragma unroll
        for (int j = 0; j < 4; j++) acc[i][j] = 0ull;

    for (int k0 = 0; k0 < K; k0 += BK) {
        float4 av = *reinterpret_cast<const float4*>(A + (size_t)(m0 + r) * K + k0 + c4 * 4);
        float4 bv = *reinterpret_cast<const float4*>(W + (size_t)(n0 + r) * K + k0 + c4 * 4);
        __syncthreads();
        As[c4 * 4 + 0][r] = av.x; As[c4 * 4 + 1][r] = av.y;
        As[c4 * 4 + 2][r] = av.z; As[c4 * 4 + 3][r] = av.w;
        Bs[c4 * 4 + 0][r] = bv.x; Bs[c4 * 4 + 1][r] = bv.y;
        Bs[c4 * 4 + 2][r] = bv.z; Bs[c4 * 4 + 3][r] = bv.w;
        __syncthreads();
#pragma unroll
        for (int k = 0; k < BK; k++) {
            float4 a = *reinterpret_cast<const float4*>(&As[k][ctm * 4]);
            float4 b = *reinterpret_cast<const float4*>(&Bs[k][ctn * 4]);
            unsigned long long ap0 = pack2(a.x, a.y);
            unsigned long long ap1 = pack2(a.z, a.w);
            unsigned long long b0 = splat2(b.x), b1 = splat2(b.y);
            unsigned long long b2 = splat2(b.z), b3 = splat2(b.w);
            ffma2(acc[0][0], ap0, b0); ffma2(acc[0][1], ap0, b1);
            ffma2(acc[0][2], ap0, b2); ffma2(acc[0][3], ap0, b3);
            ffma2(acc[1][0], ap1, b0); ffma2(acc[1][1], ap1, b1);
            ffma2(acc[1][2], ap1, b2); ffma2(acc[1][3], ap1, b3);
        }
    }

    float bia[4];
#pragma unroll
    for (int j = 0; j < 4; j++) {
        int n = n0 + ctn * 4 + j;
        bia[j] = bias1[n] + bias2[n];
    }
#pragma unroll
    for (int mp = 0; mp < 2; mp++) {
        float4 v0, v1;
        v0.x = lo32(acc[mp][0]) + bia[0]; v0.y = lo32(acc[mp][1]) + bia[1];
        v0.z = lo32(acc[mp][2]) + bia[2]; v0.w = lo32(acc[mp][3]) + bia[3];
        v1.x = hi32(acc[mp][0]) + bia[0]; v1.y = hi32(acc[mp][1]) + bia[1];
        v1.z = hi32(acc[mp][2]) + bia[2]; v1.w = hi32(acc[mp][3]) + bia[3];
        int m = m0 + ctm * 4 + mp * 2;
        *reinterpret_cast<float4*>(C + (size_t)m       * H_ + n0 + ctn * 4) = v0;
        *reinterpret_cast<float4*>(C + (size_t)(m + 1) * H_ + n0 + ctn * 4) = v1;
    }
}

// ---------------------------------------------------------------------------
// Recurrent scan, R9 core + st.async exchange (R10).
//
// One 8-CTA cluster owns 4 batch chains. CTA rank r owns hidden rows
// j in [r*64, r*64+64). 512 threads (16 warps): thread (jp = tid&31,
// ks = tid>>5) computes rows j = jp*2, jp*2+1 over k-chunk [ks*32, ks*32+32)
// for all 4 chains; W slice register-resident (64 regs/thread).
//
// h-exchange: producers (tid<256) write the local slice into hs, sync, then
// each producer LDS.128s one float4 of the slice and ships it to its 2
// assigned peer ranks with st.async.shared::cluster (direct SM->SM fabric
// store + remote mbarrier tx — NO TMA/bulk engine queue on the critical
// path). 448 x 16B per CTA per step = 7168 tx bytes, same mbarrier
// accounting as R9: consumers wait on their LOCAL mbarrier; two mbarriers +
// double-buffered hs give phase separation.
// ---------------------------------------------------------------------------
template <bool WRITE_ALL>
__global__ __launch_bounds__(512, 1) __cluster_dims__(8, 1, 1)
void scan_kernel(float* __restrict__ xw, const float* __restrict__ Whh)
{
    __shared__ alignas(16) float hs[2][8 * 256];   // 16 KB, rank-major h
    __shared__ alignas(16) float red[16][260];     // 16.6 KB partials
    __shared__ alignas(8) unsigned long long mbar[2];

    const int tid  = threadIdx.x;
    const int rank = blockIdx.x & 7;
    const int cb   = (blockIdx.x >> 3) * 4;   // first chain of this cluster
    const int jp   = tid & 31;                // j-pair index (rows 2jp, 2jp+1)
    const int ks   = tid >> 5;                // k-chunk 0..15 (== warp id)
    const int jg0  = rank * 64 + jp * 2;      // first owned W row
    const int k0   = ks * 32;

    // W_hh rows jg0, jg0+1 over k-chunk -> registers (persistent).
    ulonglong2 Wa[8], Wb[8];
    {
        const ulonglong2* w0 =
            reinterpret_cast<const ulonglong2*>(Whh + (size_t)jg0 * H_ + k0);
        const ulonglong2* w1 =
            reinterpret_cast<const ulonglong2*>(Whh + (size_t)(jg0 + 1) * H_ + k0);
#pragma unroll
        for (int i = 0; i < 8; i++) { Wa[i] = w0[i]; Wb[i] = w1[i]; }
    }

    // Output role (tid < 256): chain c = tid>>6, j = tid&63, out index = tid.
    const int oc = (tid >> 6) & 3;
    const int oj = tid & 63;
    float* own = xw + (size_t)(cb + oc) * T_ * H_ + rank * 64 + oj;
    const bool is_prod = (tid < 256);

    const uint32_t mb0  = smem_u32(&mbar[0]);
    const uint32_t mb1  = smem_u32(&mbar[1]);
    const uint32_t hsd0 = smem_u32(&hs[0][rank * 256]);   // my slice, buf0
    constexpr uint32_t HS_BUFB = 8 * 256 * 4;             // bytes per hs buf

    // Publish role: producer thread ships float4 #(tid&63) of the slice to
    // ranks rA = tid>>6 and rA+4 (skipping self).
    const int rA = (tid >> 6) & 3;
    const int rB = rA + 4;
    const uint32_t sl_off = (uint32_t)(tid & 63) * 16u;   // float4 byte offset

    if (tid == 0) {
        mbar_init(mb0, 1);
        mbar_init(mb1, 1);
        mbar_arrive_expect_tx(mb0, 7168);   // arm step 0 (7 peer slices)
        mbar_arrive_expect_tx(mb1, 7168);   // arm step 1
    }
    __syncthreads();
    cluster_sync();                          // mbarriers live before any tx

    // h-chunk base offset inside a buffer for this thread's k-range:
    const int hoff = (ks >> 1) * 256 + (ks & 1) * 32;

    // ---- t = 0: h0 = tanh(xw[0]); local slice + publish into buf 0 ----
    {
        if (is_prod) {
            float v = tanh_acc(own[0]);
            if (WRITE_ALL) own[0] = v;
            hs[0][rank * 256 + tid] = v;     // slice layout = chain*64 + j
        }
        __syncthreads();
        if (is_prod) {
            uint4 val = *reinterpret_cast<const uint4*>(
                reinterpret_cast<const char*>(&hs[0][rank * 256]) + sl_off);
            if (rA != rank) st_async_v4(hsd0 + sl_off, mb0, rA, val);
            if (rB != rank) st_async_v4(hsd0 + sl_off, mb0, rB, val);
        }
    }

    for (int t = 1; t < T_; t++) {
        // Prefetch xW(t) (independent of h(t-1)).
        float xwt = is_prod ? own[(size_t)t * H_] : 0.0f;

        const int s = t - 1;                 // step whose data we consume
        const int b = s & 1;
        const uint32_t mb = b ? mb1 : mb0;
        mbar_wait(mb, (uint32_t)((s >> 1) & 1));
        // Re-arm this mbarrier for step t+1 (its next phase), if published.
        if (tid == 0 && t <= T_ - 3) mbar_arrive_expect_tx(mb, 7168);

        // Compute: h(t-1) in hs[b]. 4 chains x 2 rows, k-chunk of 32.
        const float* hb = hs[b] + hoff;
        const ulonglong2* p0 = reinterpret_cast<const ulonglong2*>(hb + 0 * 64);
        const ulonglong2* p1 = reinterpret_cast<const ulonglong2*>(hb + 1 * 64);
        const ulonglong2* p2 = reinterpret_cast<const ulonglong2*>(hb + 2 * 64);
        const ulonglong2* p3 = reinterpret_cast<const ulonglong2*>(hb + 3 * 64);

        unsigned long long a00 = 0ull, a01 = 0ull;   // chain 0, rows 0/1
        unsigned long long a10 = 0ull, a11 = 0ull;
        unsigned long long a20 = 0ull, a21 = 0ull;
        unsigned long long a30 = 0ull, a31 = 0ull;
#pragma unroll
        for (int i = 0; i < 8; i++) {
            ulonglong2 w0 = Wa[i], w1 = Wb[i];
            ulonglong2 v0 = p0[i];
            ffma2(a00, v0.x, w0.x); ffma2(a00, v0.y, w0.y);
            ffma2(a01, v0.x, w1.x); ffma2(a01, v0.y, w1.y);
            ulonglong2 v1 = p1[i];
            ffma2(a10, v1.x, w0.x); ffma2(a10, v1.y, w0.y);
            ffma2(a11, v1.x, w1.x); ffma2(a11, v1.y, w1.y);
            ulonglong2 v2 = p2[i];
            ffma2(a20, v2.x, w0.x); ffma2(a20, v2.y, w0.y);
            ffma2(a21, v2.x, w1.x); ffma2(a21, v2.y, w1.y);
            ulonglong2 v3 = p3[i];
            ffma2(a30, v3.x, w0.x); ffma2(a30, v3.y, w0.y);
            ffma2(a31, v3.x, w1.x); ffma2(a31, v3.y, w1.y);
        }
        {
            const int j0 = jp * 2, j1 = jp * 2 + 1;
            red[ks][0 * 64 + j0] = lo32(a00) + hi32(a00);
            red[ks][0 * 64 + j1] = lo32(a01) + hi32(a01);
            red[ks][1 * 64 + j0] = lo32(a10) + hi32(a10);
            red[ks][1 * 64 + j1] = lo32(a11) + hi32(a11);
            red[ks][2 * 64 + j0] = lo32(a20) + hi32(a20);
            red[ks][2 * 64 + j1] = lo32(a21) + hi32(a21);
            red[ks][3 * 64 + j0] = lo32(a30) + hi32(a30);
            red[ks][3 * 64 + j1] = lo32(a31) + hi32(a31);
        }
        __syncthreads();

        if (is_prod) {
            float s0 = red[0][tid]  + red[1][tid]  + red[2][tid]  + red[3][tid];
            float s1 = red[4][tid]  + red[5][tid]  + red[6][tid]  + red[7][tid];
            float s2 = red[8][tid]  + red[9][tid]  + red[10][tid] + red[11][tid];
            float s3 = red[12][tid] + red[13][tid] + red[14][tid] + red[15][tid];
            float v = tanh_acc(((s0 + s1) + (s2 + s3)) + xwt);

            if (WRITE_ALL || t == T_ - 1)
                own[(size_t)t * H_] = v;      // global h (next layer / FC)

            if (t <= T_ - 2)
                hs[t & 1][rank * 256 + tid] = v;
        }
        __syncthreads();                      // slice complete / red[] safe

        if (t <= T_ - 2 && is_prod) {
            const int pb = t & 1;
            const uint32_t boff = pb ? HS_BUFB : 0u;
            const uint32_t pmb  = pb ? mb1 : mb0;
            uint4 val = *reinterpret_cast<const uint4*>(
                reinterpret_cast<const char*>(&hs[pb][rank * 256]) + sl_off);
            if (rA != rank) st_async_v4(hsd0 + boff + sl_off, pmb, rA, val);
            if (rB != rank) st_async_v4(hsd0 + boff + sl_off, pmb, rB, val);
        }
    }

    cluster_sync();   // keep smem alive until all inbound stores retired
}

// ---------------------------------------------------------------------------
// FC: out[b][o] = h1_final[b] . W_fc[o] + b_fc[o]
// ---------------------------------------------------------------------------
__global__ __launch_bounds__(256)
void fc_kernel(const float* __restrict__ hsrc,
               const float* __restrict__ Wfc,
               const float* __restrict__ bfc,
               float* __restrict__ out)
{
    __shared__ float hb[H_];
    const int b = blockIdx.x;
    const int o = threadIdx.x;
    for (int i = o; i < H_; i += 256)
        hb[i] = hsrc[((size_t)b * T_ + (T_ - 1)) * H_ + i];
    __syncthreads();

    const float4* w = reinterpret_cast<const float4*>(Wfc + (size_t)o * H_);
    float acc = 0.0f;
#pragma unroll 8
    for (int i = 0; i < H_ / 4; i++) {
        float4 wv = w[i];
        acc += hb[4 * i + 0] * wv.x + hb[4 * i + 1] * wv.y
             + hb[4 * i + 2] * wv.z + hb[4 * i + 3] * wv.w;
    }
    out[(size_t)b * O_ + o] = acc + bfc[o];
}

// ---------------------------------------------------------------------------
// kernel_launch: 5 graph-capturable kernel launches, stream-ordered.
// ---------------------------------------------------------------------------
extern "C" void kernel_launch(void* const* d_in, const int* in_sizes, int n_in,
                              void* d_out, int out_size)
{
    (void)in_sizes; (void)n_in; (void)out_size;
    const float* x    = (const float*)d_in[0];
    const float* Wih0 = (const float*)d_in[1];
    const float* Whh0 = (const float*)d_in[2];
    const float* bih0 = (const float*)d_in[3];
    const float* bhh0 = (const float*)d_in[4];
    const float* Wih1 = (const float*)d_in[5];
    const float* Whh1 = (const float*)d_in[6];
    const float* bih1 = (const float*)d_in[7];
    const float* bhh1 = (const float*)d_in[8];
    const float* Wfc  = (const float*)d_in[9];
    const float* bfc  = (const float*)d_in[10];

    float *xw = nullptr, *x2 = nullptr;
    cudaGetSymbolAddress((void**)&xw, g_xw);
    cudaGetSymbolAddress((void**)&x2, g_x2);

    dim3 ggrid(MROWS / 64, H_ / 64);   // (1024, 8)

    // Layer 0: input projection (+ both biases), then in-place recurrent scan.
    gemm_kernel<D_><<<ggrid, 256>>>(x, Wih0, bih0, bhh0, xw);
    scan_kernel<true><<<128, 512>>>(xw, Whh0);

    // Layer 1: input projection reads h0 (stored in g_xw), then scan
    // (writes only the final hidden state).
    gemm_kernel<H_><<<ggrid, 256>>>(xw, Wih1, bih1, bhh1, x2);
    scan_kernel<false><<<128, 512>>>(x2, Whh1);

    // FC on final hidden state of layer 1.
    fc_kernel<<<B_, 256>>>(x2, Wfc, bfc, (float*)d_out);
}

// round 12
// speedup vs baseline: 2.7594x; 1.1391x over previous
#include <cuda_runtime.h>
#include <cuda_bf16.h>
#include <cstdint>

// Problem dims
#define B_  64
#define T_  1024
#define D_  256
#define H_  512
#define O_  256
#define MROWS (B_ * T_)   // 65536

// ---------------------------------------------------------------------------
// Scratch (allocation-free per harness rules)
// ---------------------------------------------------------------------------
__device__ float g_xw[(size_t)B_ * T_ * H_];
__device__ float g_x2[(size_t)B_ * T_ * H_];
__device__ __nv_bfloat16 g_ah[(size_t)MROWS * H_];   // A-hi (bf16)
__device__ __nv_bfloat16 g_al[(size_t)MROWS * H_];   // A-lo (bf16 residual)
__device__ __nv_bfloat16 g_wh[(size_t)H_ * H_];      // W-hi
__device__ __nv_bfloat16 g_wl[(size_t)H_ * H_];      // W-lo

// ---------------------------------------------------------------------------
// Helpers
// ---------------------------------------------------------------------------
__device__ __forceinline__ void ffma2(unsigned long long &acc,
                                      unsigned long long a,
                                      unsigned long long b) {
    asm("fma.rn.f32x2 %0, %1, %2, %0;" : "+l"(acc) : "l"(a), "l"(b));
}
__device__ __forceinline__ float lo32(unsigned long long u) {
    return __uint_as_float((unsigned)(u & 0xffffffffull));
}
__device__ __forceinline__ float hi32(unsigned long long u) {
    return __uint_as_float((unsigned)(u >> 32));
}
__device__ __forceinline__ float tanh_acc(float x) {
    float a = fabsf(x);
    float e = __expf(-2.0f * a);
    float r = (1.0f - e) / (1.0f + e);
    return (x < 0.0f) ? -r : r;
}
__device__ __forceinline__ uint32_t smem_u32(const void* p) {
    uint32_t a;
    asm("{ .reg .u64 t; cvta.to.shared.u64 t, %1; cvt.u32.u64 %0, t; }"
        : "=r"(a) : "l"(p));
    return a;
}

// ---- mbarrier / DSMEM primitives (scan) ----
__device__ __forceinline__ void mbar_init(uint32_t addr, uint32_t count) {
    asm volatile("mbarrier.init.shared.b64 [%0], %1;" :: "r"(addr), "r"(count) : "memory");
}
__device__ __forceinline__ void mbar_arrive_expect_tx(uint32_t addr, uint32_t bytes) {
    asm volatile("mbarrier.arrive.expect_tx.shared.b64 _, [%0], %1;"
                 :: "r"(addr), "r"(bytes) : "memory");
}
__device__ __forceinline__ void mbar_wait(uint32_t addr, uint32_t parity) {
    asm volatile(
        "{\n\t"
        ".reg .pred P;\n\t"
        "WL_%=:\n\t"
        "mbarrier.try_wait.parity.acquire.cta.shared::cta.b64 P, [%0], %1, 0x989680;\n\t"
        "@!P bra WL_%=;\n\t"
        "}"
        :: "r"(addr), "r"(parity) : "memory");
}
__device__ __forceinline__ void st_async_v4(uint32_t dst_local, uint32_t mbar_local,
                                            int rank, uint4 v) {
    uint32_t dst, rmb;
    asm volatile("mapa.shared::cluster.u32 %0, %1, %2;" : "=r"(dst) : "r"(dst_local), "r"(rank));
    asm volatile("mapa.shared::cluster.u32 %0, %1, %2;" : "=r"(rmb) : "r"(mbar_local), "r"(rank));
    asm volatile(
        "st.async.shared::cluster.mbarrier::complete_tx::bytes.v4.b32 "
        "[%0], {%1, %2, %3, %4}, [%5];"
        :: "r"(dst), "r"(v.x), "r"(v.y), "r"(v.z), "r"(v.w), "r"(rmb) : "memory");
}
__device__ __forceinline__ void cluster_sync() {
    asm volatile("barrier.cluster.arrive.aligned;" ::: "memory");
    asm volatile("barrier.cluster.wait.aligned;"   ::: "memory");
}

// ---- ldmatrix / mma.sync (sm_80-era PTX; legal on compute_103) ----
__device__ __forceinline__ void ldsm_x4(uint32_t &r0, uint32_t &r1,
                                        uint32_t &r2, uint32_t &r3, uint32_t addr) {
    asm volatile("ldmatrix.sync.aligned.m8n8.x4.shared.b16 {%0,%1,%2,%3}, [%4];"
                 : "=r"(r0), "=r"(r1), "=r"(r2), "=r"(r3) : "r"(addr));
}
__device__ __forceinline__ void ldsm_x2(uint32_t &r0, uint32_t &r1, uint32_t addr) {
    asm volatile("ldmatrix.sync.aligned.m8n8.x2.shared.b16 {%0,%1}, [%2];"
                 : "=r"(r0), "=r"(r1) : "r"(addr));
}
__device__ __forceinline__ void mma16816(float &d0, float &d1, float &d2, float &d3,
                                         uint32_t a0, uint32_t a1, uint32_t a2, uint32_t a3,
                                         uint32_t b0, uint32_t b1) {
    asm volatile(
        "mma.sync.aligned.m16n8k16.row.col.f32.bf16.bf16.f32 "
        "{%0,%1,%2,%3}, {%4,%5,%6,%7}, {%8,%9}, {%0,%1,%2,%3};"
        : "+f"(d0), "+f"(d1), "+f"(d2), "+f"(d3)
        : "r"(a0), "r"(a1), "r"(a2), "r"(a3), "r"(b0), "r"(b1));
}

// ---------------------------------------------------------------------------
// fp32 -> (bf16 hi, bf16 lo) split conversion, 4 elems/thread.
// ---------------------------------------------------------------------------
__global__ __launch_bounds__(256)
void conv_split(const float* __restrict__ src,
                __nv_bfloat16* __restrict__ hi,
                __nv_bfloat16* __restrict__ lo)
{
    size_t i = ((size_t)blockIdx.x * 256 + threadIdx.x) * 4;
    float4 v = *reinterpret_cast<const float4*>(src + i);
    __nv_bfloat16 h0 = __float2bfloat16(v.x), h1 = __float2bfloat16(v.y);
    __nv_bfloat16 h2 = __float2bfloat16(v.z), h3 = __float2bfloat16(v.w);
    __nv_bfloat16 l0 = __float2bfloat16(v.x - __bfloat162float(h0));
    __nv_bfloat16 l1 = __float2bfloat16(v.y - __bfloat162float(h1));
    __nv_bfloat16 l2 = __float2bfloat16(v.z - __bfloat162float(h2));
    __nv_bfloat16 l3 = __float2bfloat16(v.w - __bfloat162float(h3));
    __nv_bfloat162 hp0(h0, h1), hp1(h2, h3), lp0(l0, l1), lp1(l2, l3);
    *reinterpret_cast<uint2*>(hi + i) =
        make_uint2(*reinterpret_cast<uint32_t*>(&hp0), *reinterpret_cast<uint32_t*>(&hp1));
    *reinterpret_cast<uint2*>(lo + i) =
        make_uint2(*reinterpret_cast<uint32_t*>(&lp0), *reinterpret_cast<uint32_t*>(&lp1));
}

// ---------------------------------------------------------------------------
// HMMA GEMM: C[M,512] = A[M,K] @ W[512,K]^T + bias1 + bias2  (fp32-split:
// 3 passes Ah*Wh + Al*Wh + Ah*Wl accumulated in fp32 registers).
// CTA tile 128x128, 8 warps (2M x 4N), warp tile 64x32 via m16n8k16.
// K streamed in 64-element SW128 chunks; with 128B rows the swizzle is
// off ^ ((row&7)<<4), linear in k -> cheap ldmatrix addressing.
// ---------------------------------------------------------------------------
template <int K>
__global__ __launch_bounds__(256)
void mma_gemm(const __nv_bfloat16* __restrict__ Ah,
              const __nv_bfloat16* __restrict__ Al,
              const __nv_bfloat16* __restrict__ Wh,
              const __nv_bfloat16* __restrict__ Wl,
              const float* __restrict__ bias1,
              const float* __restrict__ bias2,
              float* __restrict__ C)
{
    __shared__ alignas(1024) unsigned char smA[16384];   // 128 rows x 64 bf16
    __shared__ alignas(1024) unsigned char smB[16384];

    const int tid  = threadIdx.x;
    const int wid  = tid >> 5;
    const int lane = tid & 31;
    const int m0   = blockIdx.x * 128;
    const int n0   = blockIdx.y * 128;
    const int wm0  = (wid >> 2) * 64;    // warp M offset in tile
    const int wn0  = (wid & 3) * 32;     // warp N offset in tile

    // Per-lane ldmatrix addressing constants (swizzled, see header comment).
    const uint32_t a_s = smem_u32(smA), b_s = smem_u32(smB);
    const int rowA = lane & 15;                   // row within 16-row m-frag
    const int kA8  = (lane & 16) ? 16 : 0;        // byte offset of k-half
    const uint32_t xorA = (uint32_t)(rowA & 7) << 4;
    const uint32_t baseA = (uint32_t)(wm0 + rowA) * 128 + kA8;
    const int rowB = lane & 7;
    const int kB8  = (lane & 8) ? 16 : 0;
    const uint32_t xorB = (uint32_t)(rowB & 7) << 4;
    const uint32_t baseB = (uint32_t)(wn0 + rowB) * 128 + kB8;

    float acc[4][4][4];
#pragma unroll
    for (int f = 0; f < 4; f++)
#pragma unroll
        for (int g = 0; g < 4; g++)
#pragma unroll
            for (int e = 0; e < 4; e++) acc[f][g][e] = 0.0f;

    constexpr int CH  = K / 64;
    constexpr int NIT = 3 * CH;

    // Global-load role: thread covers segment s = tid + 256*i (16B each).
    for (int it = 0; it < NIT; it++) {
        const int p  = it / CH;
        const int kc = it % CH;
        const __nv_bfloat16* As = (p == 1) ? Al : Ah;
        const __nv_bfloat16* Bs = (p == 2) ? Wl : Wh;

        uint4 va[4], vb[4];
#pragma unroll
        for (int i = 0; i < 4; i++) {
            int s   = tid + 256 * i;
            int row = s >> 3, seg = s & 7;
            va[i] = *reinterpret_cast<const uint4*>(
                As + (size_t)(m0 + row) * K + kc * 64 + seg * 8);
            vb[i] = *reinterpret_cast<const uint4*>(
                Bs + (size_t)(n0 + row) * K + kc * 64 + seg * 8);
        }
        __syncthreads();   // previous chunk's smem reads complete
#pragma unroll
        for (int i = 0; i < 4; i++) {
            int s   = tid + 256 * i;
            int row = s >> 3, seg = s & 7;
            uint32_t off = (uint32_t)(row * 128 + seg * 16);
            off ^= ((off >> 3) & 0x70);
            *reinterpret_cast<uint4*>(smA + off) = va[i];
            *reinterpret_cast<uint4*>(smB + off) = vb[i];
        }
        __syncthreads();

        // 4 k-steps of 16 over this 64-wide chunk.
#pragma unroll
        for (int ks = 0; ks < 4; ks++) {
            uint32_t af[4][4], bf[4][2];
#pragma unroll
            for (int f = 0; f < 4; f++) {
                uint32_t addr = a_s + (((baseA + (uint32_t)(f * 2048 + ks * 32)) ^ xorA));
                ldsm_x4(af[f][0], af[f][1], af[f][2], af[f][3], addr);
            }
#pragma unroll
            for (int g = 0; g < 4; g++) {
                uint32_t addr = b_s + (((baseB + (uint32_t)(g * 1024 + ks * 32)) ^ xorB));
                ldsm_x2(bf[g][0], bf[g][1], addr);
            }
#pragma unroll
            for (int f = 0; f < 4; f++)
#pragma unroll
                for (int g = 0; g < 4; g++)
                    mma16816(acc[f][g][0], acc[f][g][1], acc[f][g][2], acc[f][g][3],
                             af[f][0], af[f][1], af[f][2], af[f][3],
                             bf[g][0], bf[g][1]);
        }
    }

    // Epilogue: direct STG with bias. Lane (r = lane>>2, c4 = lane&3):
    // c0,c1 -> row r,  cols 2c4, 2c4+1 ; c2,c3 -> row r+8, same cols.
    const int r  = lane >> 2;
    const int c4 = lane & 3;
#pragma unroll
    for (int g = 0; g < 4; g++) {
        const int n = n0 + wn0 + g * 8 + c4 * 2;
        float2 bsum;
        bsum.x = bias1[n]     + bias2[n];
        bsum.y = bias1[n + 1] + bias2[n + 1];
#pragma unroll
        for (int f = 0; f < 4; f++) {
            const int mr = m0 + wm0 + f * 16 + r;
            float2 v0, v1;
            v0.x = acc[f][g][0] + bsum.x; v0.y = acc[f][g][1] + bsum.y;
            v1.x = acc[f][g][2] + bsum.x; v1.y = acc[f][g][3] + bsum.y;
            *reinterpret_cast<float2*>(C + (size_t)mr * H_ + n)       = v0;
            *reinterpret_cast<float2*>(C + (size_t)(mr + 8) * H_ + n) = v1;
        }
    }
}

// ---------------------------------------------------------------------------
// Recurrent scan — unchanged (mbarrier dataflow + st.async exchange).
// ---------------------------------------------------------------------------
template <bool WRITE_ALL>
__global__ __launch_bounds__(512, 1) __cluster_dims__(8, 1, 1)
void scan_kernel(float* __restrict__ xw, const float* __restrict__ Whh)
{
    __shared__ alignas(16) float hs[2][8 * 256];
    __shared__ alignas(16) float red[16][260];
    __shared__ alignas(8) unsigned long long mbar[2];

    const int tid  = threadIdx.x;
    const int rank = blockIdx.x & 7;
    const int cb   = (blockIdx.x >> 3) * 4;
    const int jp   = tid & 31;
    const int ks   = tid >> 5;
    const int jg0  = rank * 64 + jp * 2;
    const int k0   = ks * 32;

    ulonglong2 Wa[8], Wb[8];
    {
        const ulonglong2* w0 =
            reinterpret_cast<const ulonglong2*>(Whh + (size_t)jg0 * H_ + k0);
        const ulonglong2* w1 =
            reinterpret_cast<const ulonglong2*>(Whh + (size_t)(jg0 + 1) * H_ + k0);
#pragma unroll
        for (int i = 0; i < 8; i++) { Wa[i] = w0[i]; Wb[i] = w1[i]; }
    }

    const int oc = (tid >> 6) & 3;
    const int oj = tid & 63;
    float* own = xw + (size_t)(cb + oc) * T_ * H_ + rank * 64 + oj;
    const bool is_prod = (tid < 256);

    const uint32_t mb0  = smem_u32(&mbar[0]);
    const uint32_t mb1  = smem_u32(&mbar[1]);
    const uint32_t hsd0 = smem_u32(&hs[0][rank * 256]);
    constexpr uint32_t HS_BUFB = 8 * 256 * 4;

    const int rA = (tid >> 6) & 3;
    const int rB = rA + 4;
    const uint32_t sl_off = (uint32_t)(tid & 63) * 16u;

    if (tid == 0) {
        mbar_init(mb0, 1);
        mbar_init(mb1, 1);
        mbar_arrive_expect_tx(mb0, 7168);
        mbar_arrive_expect_tx(mb1, 7168);
    }
    __syncthreads();
    cluster_sync();

    const int hoff = (ks >> 1) * 256 + (ks & 1) * 32;

    {
        if (is_prod) {
            float v = tanh_acc(own[0]);
            if (WRITE_ALL) own[0] = v;
            hs[0][rank * 256 + tid] = v;
        }
        __syncthreads();
        if (is_prod) {
            uint4 val = *reinterpret_cast<const uint4*>(
                reinterpret_cast<const char*>(&hs[0][rank * 256]) + sl_off);
            if (rA != rank) st_async_v4(hsd0 + sl_off, mb0, rA, val);
            if (rB != rank) st_async_v4(hsd0 + sl_off, mb0, rB, val);
        }
    }

    for (int t = 1; t < T_; t++) {
        float xwt = is_prod ? own[(size_t)t * H_] : 0.0f;

        const int s = t - 1;
        const int b = s & 1;
        const uint32_t mb = b ? mb1 : mb0;
        mbar_wait(mb, (uint32_t)((s >> 1) & 1));
        if (tid == 0 && t <= T_ - 3) mbar_arrive_expect_tx(mb, 7168);

        const float* hb = hs[b] + hoff;
        const ulonglong2* p0 = reinterpret_cast<const ulonglong2*>(hb + 0 * 64);
        const ulonglong2* p1 = reinterpret_cast<const ulonglong2*>(hb + 1 * 64);
        const ulonglong2* p2 = reinterpret_cast<const ulonglong2*>(hb + 2 * 64);
        const ulonglong2* p3 = reinterpret_cast<const ulonglong2*>(hb + 3 * 64);

        unsigned long long a00 = 0ull, a01 = 0ull;
        unsigned long long a10 = 0ull, a11 = 0ull;
        unsigned long long a20 = 0ull, a21 = 0ull;
        unsigned long long a30 = 0ull, a31 = 0ull;
#pragma unroll
        for (int i = 0; i < 8; i++) {
            ulonglong2 w0 = Wa[i], w1 = Wb[i];
            ulonglong2 v0 = p0[i];
            ffma2(a00, v0.x, w0.x); ffma2(a00, v0.y, w0.y);
            ffma2(a01, v0.x, w1.x); ffma2(a01, v0.y, w1.y);
            ulonglong2 v1 = p1[i];
            ffma2(a10, v1.x, w0.x); ffma2(a10, v1.y, w0.y);
            ffma2(a11, v1.x, w1.x); ffma2(a11, v1.y, w1.y);
            ulonglong2 v2 = p2[i];
            ffma2(a20, v2.x, w0.x); ffma2(a20, v2.y, w0.y);
            ffma2(a21, v2.x, w1.x); ffma2(a21, v2.y, w1.y);
            ulonglong2 v3 = p3[i];
            ffma2(a30, v3.x, w0.x); ffma2(a30, v3.y, w0.y);
            ffma2(a31, v3.x, w1.x); ffma2(a31, v3.y, w1.y);
        }
        {
            const int j0 = jp * 2, j1 = jp * 2 + 1;
            red[ks][0 * 64 + j0] = lo32(a00) + hi32(a00);
            red[ks][0 * 64 + j1] = lo32(a01) + hi32(a01);
            red[ks][1 * 64 + j0] = lo32(a10) + hi32(a10);
            red[ks][1 * 64 + j1] = lo32(a11) + hi32(a11);
            red[ks][2 * 64 + j0] = lo32(a20) + hi32(a20);
            red[ks][2 * 64 + j1] = lo32(a21) + hi32(a21);
            red[ks][3 * 64 + j0] = lo32(a30) + hi32(a30);
            red[ks][3 * 64 + j1] = lo32(a31) + hi32(a31);
        }
        __syncthreads();

        if (is_prod) {
            float s0 = red[0][tid]  + red[1][tid]  + red[2][tid]  + red[3][tid];
            float s1 = red[4][tid]  + red[5][tid]  + red[6][tid]  + red[7][tid];
            float s2 = red[8][tid]  + red[9][tid]  + red[10][tid] + red[11][tid];
            float s3 = red[12][tid] + red[13][tid] + red[14][tid] + red[15][tid];
            float v = tanh_acc(((s0 + s1) + (s2 + s3)) + xwt);

            if (WRITE_ALL || t == T_ - 1)
                own[(size_t)t * H_] = v;

            if (t <= T_ - 2)
                hs[t & 1][rank * 256 + tid] = v;
        }
        __syncthreads();

        if (t <= T_ - 2 && is_prod) {
            const int pb = t & 1;
            const uint32_t boff = pb ? HS_BUFB : 0u;
            const uint32_t pmb  = pb ? mb1 : mb0;
            uint4 val = *reinterpret_cast<const uint4*>(
                reinterpret_cast<const char*>(&hs[pb][rank * 256]) + sl_off);
            if (rA != rank) st_async_v4(hsd0 + boff + sl_off, pmb, rA, val);
            if (rB != rank) st_async_v4(hsd0 + boff + sl_off, pmb, rB, val);
        }
    }

    cluster_sync();
}

// ---------------------------------------------------------------------------
// FC: out[b][o] = h1_final[b] . W_fc[o] + b_fc[o]
// ---------------------------------------------------------------------------
__global__ __launch_bounds__(256)
void fc_kernel(const float* __restrict__ hsrc,
               const float* __restrict__ Wfc,
               const float* __restrict__ bfc,
               float* __restrict__ out)
{
    __shared__ float hb[H_];
    const int b = blockIdx.x;
    const int o = threadIdx.x;
    for (int i = o; i < H_; i += 256)
        hb[i] = hsrc[((size_t)b * T_ + (T_ - 1)) * H_ + i];
    __syncthreads();

    const float4* w = reinterpret_cast<const float4*>(Wfc + (size_t)o * H_);
    float acc = 0.0f;
#pragma unroll 8
    for (int i = 0; i < H_ / 4; i++) {
        float4 wv = w[i];
        acc += hb[4 * i + 0] * wv.x + hb[4 * i + 1] * wv.y
             + hb[4 * i + 2] * wv.z + hb[4 * i + 3] * wv.w;
    }
    out[(size_t)b * O_ + o] = acc + bfc[o];
}

// ---------------------------------------------------------------------------
// kernel_launch: 9 graph-capturable kernel launches, stream-ordered.
// ---------------------------------------------------------------------------
extern "C" void kernel_launch(void* const* d_in, const int* in_sizes, int n_in,
                              void* d_out, int out_size)
{
    (void)in_sizes; (void)n_in; (void)out_size;
    const float* x    = (const float*)d_in[0];
    const float* Wih0 = (const float*)d_in[1];
    const float* Whh0 = (const float*)d_in[2];
    const float* bih0 = (const float*)d_in[3];
    const float* bhh0 = (const float*)d_in[4];
    const float* Wih1 = (const float*)d_in[5];
    const float* Whh1 = (const float*)d_in[6];
    const float* bih1 = (const float*)d_in[7];
    const float* bhh1 = (const float*)d_in[8];
    const float* Wfc  = (const float*)d_in[9];
    const float* bfc  = (const float*)d_in[10];

    float *xw = nullptr, *x2 = nullptr;
    __nv_bfloat16 *ah = nullptr, *al = nullptr, *wh = nullptr, *wl = nullptr;
    cudaGetSymbolAddress((void**)&xw, g_xw);
    cudaGetSymbolAddress((void**)&x2, g_x2);
    cudaGetSymbolAddress((void**)&ah, g_ah);
    cudaGetSymbolAddress((void**)&al, g_al);
    cudaGetSymbolAddress((void**)&wh, g_wh);
    cudaGetSymbolAddress((void**)&wl, g_wl);

    dim3 mgrid(MROWS / 128, H_ / 128);   // (512, 4)

    // ---- Layer 0: split-convert, HMMA input projection, scan ----
    conv_split<<<(H_ * D_) / 1024, 256>>>(Wih0, wh, wl);
    conv_split<<<((size_t)MROWS * D_) / 1024, 256>>>(x, ah, al);
    mma_gemm<D_><<<mgrid, 256>>>(ah, al, wh, wl, bih0, bhh0, xw);
    scan_kernel<true><<<128, 512>>>(xw, Whh0);

    // ---- Layer 1 ----
    conv_split<<<(H_ * H_) / 1024, 256>>>(Wih1, wh, wl);
    conv_split<<<((size_t)MROWS * H_) / 1024, 256>>>(xw, ah, al);
    mma_gemm<H_><<<mgrid, 256>>>(ah, al, wh, wl, bih1, bhh1, x2);
    scan_kernel<false><<<128, 512>>>(x2, Whh1);

    // ---- FC on final hidden state of layer 1 ----
    fc_kernel<<<B_, 256>>>(x2, Wfc, bfc, (float*)d_out);
}